// round 8
// baseline (speedup 1.0000x reference)
#include <cuda_runtime.h>
#include <cuda_bf16.h>
#include <cstdint>

#define B_    2
#define S_    2048
#define H_    16
#define DH_   64
#define DHID_ 256
#define DKER_ 64
#define D_    1024
#define BH_   (B_*H_)

// Scratch (static device globals)
__device__ uint32_t g_qf_w[BH_*S_*32];      // 8 MB  |qf| bf16x2
__device__ uint32_t g_kf_w[BH_*S_*32];      // 8 MB  |kf| bf16x2
__device__ float    g_vt  [BH_*64*S_];      // 16 MB V^T [bh][e][s], tf32-rounded
__device__ int      g_mask_mode;
__device__ uint32_t g_maskbits[B_*S_*S_/32];

__device__ __forceinline__ float to_tf32(float x) {
    uint32_t u;
    asm("cvt.rna.tf32.f32 %0, %1;" : "=r"(u) : "f"(x));
    return __uint_as_float(u);
}
__device__ __forceinline__ uint32_t packbf(float lo, float hi) {
    uint32_t r;
    asm("cvt.rn.bf16x2.f32 %0, %1, %2;" : "=r"(r) : "f"(hi), "f"(lo));
    return r;
}
__device__ __forceinline__ float gelu_t(float x) {
    float x3 = x * x * x;
    float t  = tanhf(0.7978845608028654f * (x + 0.044715f * x3));
    return 0.5f * x * (1.0f + t);
}
__device__ __forceinline__ void mma_tf32(float* c, const float* a, const float* b) {
    asm volatile(
        "mma.sync.aligned.m16n8k8.row.col.f32.tf32.tf32.f32 "
        "{%0,%1,%2,%3}, {%4,%5,%6,%7}, {%8,%9}, {%0,%1,%2,%3};\n"
        : "+f"(c[0]), "+f"(c[1]), "+f"(c[2]), "+f"(c[3])
        : "r"(__float_as_uint(a[0])), "r"(__float_as_uint(a[1])),
          "r"(__float_as_uint(a[2])), "r"(__float_as_uint(a[3])),
          "r"(__float_as_uint(b[0])), "r"(__float_as_uint(b[1])));
}
__device__ __forceinline__ void mma_bf16(float* c, const uint32_t* a, uint32_t b0, uint32_t b1) {
    asm volatile(
        "mma.sync.aligned.m16n8k16.row.col.f32.bf16.bf16.f32 "
        "{%0,%1,%2,%3}, {%4,%5,%6,%7}, {%8,%9}, {%0,%1,%2,%3};\n"
        : "+f"(c[0]), "+f"(c[1]), "+f"(c[2]), "+f"(c[3])
        : "r"(a[0]), "r"(a[1]), "r"(a[2]), "r"(a[3]),
          "r"(b0), "r"(b1));
}
__device__ __forceinline__ void ldsm_x4(uint32_t* r, uint32_t addr) {
    asm volatile("ldmatrix.sync.aligned.m8n8.x4.shared.b16 {%0,%1,%2,%3}, [%4];"
        : "=r"(r[0]), "=r"(r[1]), "=r"(r[2]), "=r"(r[3]) : "r"(addr));
}
__device__ __forceinline__ uint32_t smaddr(const void* p) {
    return (uint32_t)__cvta_generic_to_shared(p);
}
#define CPA16(dst, src) \
    asm volatile("cp.async.cg.shared.global [%0], [%1], 16;\n" :: "r"(dst), "l"(src))
#define CPA_COMMIT() asm volatile("cp.async.commit_group;\n" ::: "memory")
#define CPA_WAIT(N)  asm volatile("cp.async.wait_group %0;\n" :: "n"(N) : "memory")

// ---------------------------------------------------------------------------
__global__ void detect_mask_kernel(const uint32_t* __restrict__ m) {
    if (threadIdx.x == 0 && blockIdx.x == 0) {
        int mode = 1;
        for (int i = 0; i < 1024; i++) {
            uint32_t w = m[(size_t)i * 2048];
            if (w == 0x3f800000u) { mode = 2; break; }
            if (w > 1u)           { mode = 0; break; }
        }
        g_mask_mode = mode;
    }
}

__global__ __launch_bounds__(256)
void maskbits_kernel(const void* __restrict__ m) {
    int mode = g_mask_mode;
    int warpg = (blockIdx.x * 256 + threadIdx.x) >> 5;
    int lane  = threadIdx.x & 31;
    size_t base = (size_t)warpg * 1024;
    #pragma unroll 4
    for (int s = 0; s < 32; s++) {
        size_t idx = base + (size_t)s * 32 + lane;
        bool v;
        if (mode == 0)      v = ((const uint8_t*) m)[idx] != 0;
        else if (mode == 1) v = ((const uint32_t*)m)[idx] != 0u;
        else                v = ((const float*)   m)[idx] != 0.0f;
        unsigned w = __ballot_sync(0xffffffffu, v);
        if (lane == s) g_maskbits[base/32 + s] = w;
    }
}

// ---------------------------------------------------------------------------
// V transpose + tf32 pre-round: g_vt[bh][e][s]
// ---------------------------------------------------------------------------
__global__ __launch_bounds__(256)
void vt_kernel(const float* __restrict__ Vg) {
    __shared__ float ts[64][65];
    int bh = blockIdx.y, b = bh >> 4, h = bh & 15;
    int s0 = blockIdx.x * 64;
    int tid = threadIdx.x;
    const float* src = Vg + ((size_t)(b*S_ + s0))*D_ + h*DH_;
    for (int idx = tid; idx < 4096; idx += 256) {
        int r = idx >> 6, e = idx & 63;
        ts[e][r] = to_tf32(src[(size_t)r*D_ + e]);
    }
    __syncthreads();
    float* dst = g_vt + (size_t)bh*64*S_ + s0;
    for (int idx = tid; idx < 4096; idx += 256) {
        int e = idx >> 6, sl = idx & 63;
        dst[(size_t)e*S_ + sl] = ts[e][sl];
    }
}

// ---------------------------------------------------------------------------
// Merged fused feature maps: blockIdx.z = 0 (q path) / 1 (k path)
// ---------------------------------------------------------------------------
__global__ __launch_bounds__(256, 2)
void fused_kernel(const float* __restrict__ Xq, const float* __restrict__ Xk,
                  const float* __restrict__ Wq1, const float* __restrict__ Wk1,
                  const float* __restrict__ Wq2, const float* __restrict__ Wk2,
                  const float* __restrict__ Wint,
                  const float* __restrict__ sD, const float* __restrict__ sD2)
{
    extern __shared__ float sm[];
    float* Xs  = sm;                  // 128*68
    float* W1s = Xs  + 128*68;        // 64*68
    float* W2s = W1s + 64*68;         // 64*68
    float* T1s = W2s + 64*68;         // 128*68

    bool kpath = (blockIdx.z != 0);
    const float* X  = kpath ? Xk  : Xq;
    const float* W1 = kpath ? Wk1 : Wq1;
    const float* W2 = kpath ? Wk2 : Wq2;
    uint32_t* outg  = kpath ? g_kf_w : g_qf_w;

    int bh = blockIdx.y, b = bh >> 4, h = bh & 15;
    int m0 = blockIdx.x * 128;
    int tid = threadIdx.x;
    int warp = tid >> 5, lane = tid & 31, g = lane >> 2, tg = lane & 3;
    int wm = warp & 3, wn = warp >> 2;

    const float* Xb = X + ((size_t)(b*S_ + m0))*D_ + h*DH_;
    for (int idx = tid; idx < 128*64; idx += 256) {
        int r = idx >> 6, d = idx & 63;
        Xs[r*68 + d] = to_tf32(Xb[(size_t)r*D_ + d]);
    }

    const float* W1h = W1 + (size_t)h*DH_*DHID_;
    const float* W2h = W2 + (size_t)h*DHID_*DKER_;

    float acc2[8][4];
    #pragma unroll
    for (int j=0;j<8;j++) for (int c=0;c<4;c++) acc2[j][c]=0.f;

    for (int c0 = 0; c0 < 4; c0++) {
        int n0 = c0*64;
        for (int idx = tid; idx < 64*64; idx += 256) {
            int k = idx >> 6, n = idx & 63;
            W1s[n*68 + k] = to_tf32(W1h[(size_t)k*DHID_ + n0 + n]);
        }
        __syncthreads();

        float acc1[2][4][4];
        #pragma unroll
        for (int i=0;i<2;i++) for (int j=0;j<4;j++) for (int c=0;c<4;c++) acc1[i][j][c]=0.f;
        #pragma unroll
        for (int k0=0;k0<64;k0+=8) {
            float a[2][4], bf[4][2];
            #pragma unroll
            for (int i=0;i<2;i++) {
                int rb = wm*32 + i*16;
                a[i][0] = Xs[(rb+g  )*68 + k0+tg  ];
                a[i][1] = Xs[(rb+g+8)*68 + k0+tg  ];
                a[i][2] = Xs[(rb+g  )*68 + k0+tg+4];
                a[i][3] = Xs[(rb+g+8)*68 + k0+tg+4];
            }
            #pragma unroll
            for (int j=0;j<4;j++) {
                int nb = wn*32 + j*8 + g;
                bf[j][0] = W1s[nb*68 + k0+tg  ];
                bf[j][1] = W1s[nb*68 + k0+tg+4];
            }
            #pragma unroll
            for (int i=0;i<2;i++)
                #pragma unroll
                for (int j=0;j<4;j++)
                    mma_tf32(acc1[i][j], a[i], bf[j]);
        }
        #pragma unroll
        for (int i=0;i<2;i++) {
            #pragma unroll
            for (int j=0;j<4;j++) {
                int rr = wm*32 + i*16 + g;
                int cc = wn*32 + j*8 + 2*tg;
                *(float2*)&T1s[rr*68 + cc] =
                    make_float2(to_tf32(gelu_t(acc1[i][j][0])), to_tf32(gelu_t(acc1[i][j][1])));
                *(float2*)&T1s[(rr+8)*68 + cc] =
                    make_float2(to_tf32(gelu_t(acc1[i][j][2])), to_tf32(gelu_t(acc1[i][j][3])));
            }
        }
        for (int idx = tid; idx < 64*64; idx += 256) {
            int k = idx >> 6, n = idx & 63;
            W2s[n*68 + k] = to_tf32(W2h[(size_t)(n0 + k)*DKER_ + n]);
        }
        __syncthreads();

        #pragma unroll
        for (int k0=0;k0<64;k0+=8) {
            float a[4], bf[8][2];
            int rb = warp*16;
            a[0] = T1s[(rb+g  )*68 + k0+tg  ];
            a[1] = T1s[(rb+g+8)*68 + k0+tg  ];
            a[2] = T1s[(rb+g  )*68 + k0+tg+4];
            a[3] = T1s[(rb+g+8)*68 + k0+tg+4];
            #pragma unroll
            for (int j=0;j<8;j++) {
                int nb = j*8+g;
                bf[j][0] = W2s[nb*68 + k0+tg  ];
                bf[j][1] = W2s[nb*68 + k0+tg+4];
            }
            #pragma unroll
            for (int j=0;j<8;j++) mma_tf32(acc2[j], a, bf[j]);
        }
    }

    uint32_t* outw = outg + ((size_t)bh*S_ + m0)*32;

    if (!kpath) {
        #pragma unroll
        for (int j=0;j<8;j++) {
            int rr = warp*16 + g, wi = j*4 + tg;
            outw[(size_t)rr*32 + wi] =
                packbf(fabsf(gelu_t(acc2[j][0])), fabsf(gelu_t(acc2[j][1])));
            outw[(size_t)(rr+8)*32 + wi] =
                packbf(fabsf(gelu_t(acc2[j][2])), fabsf(gelu_t(acc2[j][3])));
        }
        return;
    }

    const float* sDh  = sD  + h*DKER_;
    const float* sD2h = sD2 + h*DKER_;
    __syncthreads();
    #pragma unroll
    for (int j=0;j<8;j++) {
        int rr = warp*16 + g, cc = j*8 + 2*tg;
        T1s[rr*68 + cc  ]     = fabsf(sDh[cc  ]) * gelu_t(acc2[j][0]);
        T1s[rr*68 + cc+1]     = fabsf(sDh[cc+1]) * gelu_t(acc2[j][1]);
        T1s[(rr+8)*68 + cc  ] = fabsf(sDh[cc  ]) * gelu_t(acc2[j][2]);
        T1s[(rr+8)*68 + cc+1] = fabsf(sDh[cc+1]) * gelu_t(acc2[j][3]);
    }
    const float* Wih = Wint + (size_t)h*DKER_*DKER_;
    for (int idx = tid; idx < 64*64; idx += 256) {
        int k = idx >> 6, n = idx & 63;
        W1s[n*68 + k] = to_tf32(Wih[(size_t)k*DKER_ + n]);
    }
    __syncthreads();

    float ac2[8][4];
    #pragma unroll
    for (int j=0;j<8;j++) for (int c=0;c<4;c++) ac2[j][c]=0.f;
    #pragma unroll
    for (int k0=0;k0<64;k0+=8) {
        float a[4], bf[8][2];
        int rb = warp*16;
        a[0] = to_tf32(T1s[(rb+g  )*68 + k0+tg  ]);
        a[1] = to_tf32(T1s[(rb+g+8)*68 + k0+tg  ]);
        a[2] = to_tf32(T1s[(rb+g  )*68 + k0+tg+4]);
        a[3] = to_tf32(T1s[(rb+g+8)*68 + k0+tg+4]);
        #pragma unroll
        for (int j=0;j<8;j++) {
            int nb = j*8+g;
            bf[j][0] = W1s[nb*68 + k0+tg  ];
            bf[j][1] = W1s[nb*68 + k0+tg+4];
        }
        #pragma unroll
        for (int j=0;j<8;j++) mma_tf32(ac2[j], a, bf[j]);
    }

    #pragma unroll
    for (int j=0;j<8;j++) {
        int rr = warp*16 + g, cc = j*8 + 2*tg;
        int wi = j*4 + tg;
        float t00 = T1s[rr*68 + cc  ],     t01 = T1s[rr*68 + cc+1];
        float t10 = T1s[(rr+8)*68 + cc],   t11 = T1s[(rr+8)*68 + cc+1];
        outw[(size_t)rr*32 + wi] =
            packbf(fabsf(t00 + ac2[j][0]*sD2h[cc  ]),
                   fabsf(t01 + ac2[j][1]*sD2h[cc+1]));
        outw[(size_t)(rr+8)*32 + wi] =
            packbf(fabsf(t10 + ac2[j][2]*sD2h[cc  ]),
                   fabsf(t11 + ac2[j][3]*sD2h[cc+1]));
    }
}

// ---------------------------------------------------------------------------
// Attention: bf16 scores (ldmatrix), tf32 PV, saw via early LDG->regs.
// Per tile t (Ps holds P(t-1), KV(t) group pending):
//   WAIT(0)+sync -> LDG saw(t)+mask -> PV(t-1) -> sync
//   -> cp.async KV(t+1) -> score MMA(t) -> epilogue regs->Ps
// smem words: Qs[128*36] Ks[2*64*36] Vts[2*64*68] Ps[128*68] rowsum[128]
// = 107008 B -> 2 CTAs/SM
// ---------------------------------------------------------------------------
__global__ __launch_bounds__(256, 2)
void attn_kernel(const float* __restrict__ sp_lse, const float* __restrict__ saw,
                 float* __restrict__ outp) {
    extern __shared__ uint32_t smw[];
    uint32_t* Qs  = smw;                     // 128*36 (bf16x2)
    uint32_t* Ks  = Qs + 128*36;             // 2*64*36 (bf16x2)
    float*    Vts = (float*)(Ks + 2*64*36);  // 2*64*68 f32 (V^T tiles [e][t])
    float*    Ps  = Vts + 2*64*68;           // 128*68 f32
    float* rowsum = Ps + 128*68;             // 128

    int bh = blockIdx.y, b = bh >> 4, h = bh & 15;
    int m0 = blockIdx.x * 128;
    int tid = threadIdx.x, warp = tid>>5, lane = tid&31, g = lane>>2, tg = lane&3;
    int wm = warp & 3, wn = warp >> 2;

    // Q tile (bf16 words)
    const uint32_t* qsrc = g_qf_w + ((size_t)bh*S_ + m0)*32;
    for (int idx = tid; idx < 4096; idx += 256) {
        int r = idx >> 5, c = idx & 31;
        Qs[r*36 + c] = qsrc[idx];
    }
    if (tid < 128) rowsum[tid] = 0.f;

    const char* kbase  = (const char*)(g_kf_w + (size_t)bh*S_*32);
    const char* vtbase = (const char*)(g_vt + (size_t)bh*64*S_);
    const float* sawb  = saw + (size_t)bh*S_*S_;

    // ldmatrix lane addressing
    int mrow = lane & 15;
    int mwo  = (lane >> 4) << 2;   // word offset within 16-bf16 step

    // prologue: KV(0)
    {
        #pragma unroll
        for (int c2 = 0; c2 < 2; c2++) {
            int qi = tid + c2*256, r = qi >> 3, cc = qi & 7;
            CPA16(smaddr(Ks + r*36) + cc*16, kbase + (size_t)r*128 + cc*16);
        }
        #pragma unroll
        for (int c2 = 0; c2 < 4; c2++) {
            int qi = tid + c2*256, r = qi >> 4, cc = qi & 15;
            CPA16(smaddr(Vts + r*68) + cc*16, vtbase + (size_t)r*(S_*4) + cc*16);
        }
        CPA_COMMIT();
    }

    float oacc[8][4];
    #pragma unroll
    for (int j=0;j<8;j++) for (int c=0;c<4;c++) oacc[j][c]=0.f;
    float rsl[2][2] = {{0.f,0.f},{0.f,0.f}};

    for (int t = 0; t < 32; t++) {
        int pt = t & 1;

        // (1) KV(t) ready; Ps(t-1) published
        CPA_WAIT(0);
        __syncthreads();

        // (2) early loads: saw(t) -> regs (16x LDG.64), mask words
        float2 sw[2][4][2];
        uint32_t mwd[2][2];
        #pragma unroll
        for (int i=0;i<2;i++) {
            int rg0 = m0 + wm*32 + i*16 + g;
            #pragma unroll
            for (int p=0;p<2;p++) {
                mwd[i][p] = g_maskbits[((size_t)(b*S_ + rg0 + 8*p))*64 + t*2 + wn];
                const float* srow = sawb + (size_t)(rg0 + 8*p)*S_ + t*64;
                #pragma unroll
                for (int j=0;j<4;j++)
                    sw[i][j][p] = *(const float2*)(srow + wn*32 + j*8 + 2*tg);
            }
        }

        // (3) PV(t-1): tf32
        if (t > 0) {
            const float* Vb = Vts + (pt^1)*64*68;
            int rb = warp*16;
            #pragma unroll
            for (int k0 = 0; k0 < 64; k0 += 8) {
                float a[4], bf[8][2];
                a[0] = Ps[(rb+g  )*68 + k0+tg  ];
                a[1] = Ps[(rb+g+8)*68 + k0+tg  ];
                a[2] = Ps[(rb+g  )*68 + k0+tg+4];
                a[3] = Ps[(rb+g+8)*68 + k0+tg+4];
                #pragma unroll
                for (int j=0;j<8;j++) {
                    bf[j][0] = Vb[(j*8+g)*68 + k0+tg  ];
                    bf[j][1] = Vb[(j*8+g)*68 + k0+tg+4];
                }
                #pragma unroll
                for (int j=0;j<8;j++) mma_tf32(oacc[j], a, bf[j]);
            }
        }
        // (4) Ps free; Vts[pt^1], Ks[pt^1] free
        __syncthreads();

        // (5) KV(t+1) cp.async into parity pt^1
        if (t < 31) {
            size_t t0n = (size_t)(t+1)*64;
            uint32_t* Kd = Ks  + (pt^1)*64*36;
            float*    Vd = Vts + (pt^1)*64*68;
            #pragma unroll
            for (int c2 = 0; c2 < 2; c2++) {
                int qi = tid + c2*256, r = qi >> 3, cc = qi & 7;
                CPA16(smaddr(Kd + r*36) + cc*16, kbase + (t0n + r)*128 + cc*16);
            }
            #pragma unroll
            for (int c2 = 0; c2 < 4; c2++) {
                int qi = tid + c2*256, r = qi >> 4, cc = qi & 15;
                CPA16(smaddr(Vd + r*68) + cc*16,
                      vtbase + (size_t)r*(S_*4) + t0n*4 + cc*16);
            }
        }
        CPA_COMMIT();

        // (6) score MMA(t): bf16 via ldmatrix
        float sacc[2][4][4];
        #pragma unroll
        for (int i=0;i<2;i++) for (int j=0;j<4;j++) for (int c=0;c<4;c++) sacc[i][j][c]=0.f;
        {
            const uint32_t* Kb = Ks + pt*64*36;
            uint32_t qa = smaddr(Qs + (wm*32 + mrow)*36 + mwo);
            uint32_t ka = smaddr(Kb + (wn*32 + mrow)*36 + mwo);
            #pragma unroll
            for (int kw = 0; kw < 32; kw += 8) {
                uint32_t a0[4], a1[4], b0[4], b1[4];
                ldsm_x4(a0, qa + kw*4);
                ldsm_x4(a1, qa + 16*36*4 + kw*4);
                ldsm_x4(b0, ka + kw*4);
                ldsm_x4(b1, ka + 16*36*4 + kw*4);
                mma_bf16(sacc[0][0], a0, b0[0], b0[2]);
                mma_bf16(sacc[0][1], a0, b0[1], b0[3]);
                mma_bf16(sacc[0][2], a0, b1[0], b1[2]);
                mma_bf16(sacc[0][3], a0, b1[1], b1[3]);
                mma_bf16(sacc[1][0], a1, b0[0], b0[2]);
                mma_bf16(sacc[1][1], a1, b0[1], b0[3]);
                mma_bf16(sacc[1][2], a1, b1[0], b1[2]);
                mma_bf16(sacc[1][3], a1, b1[1], b1[3]);
            }
        }

        // (7) epilogue: regs -> Ps (tf32)
        #pragma unroll
        for (int i=0;i<2;i++) {
            int rlb = wm*32 + i*16 + g;
            #pragma unroll
            for (int j=0;j<4;j++) {
                int cl = wn*32 + j*8 + 2*tg;
                int bit = j*8 + 2*tg;
                #pragma unroll
                for (int p=0;p<2;p++) {
                    int rr = rlb + 8*p;
                    float2 s2 = sw[i][j][p];
                    uint32_t word = mwd[i][p];
                    bool b0m = (word >> bit) & 1u;
                    bool b1m = (word >> (bit+1)) & 1u;
                    float s0 = sacc[i][j][2*p], s1 = sacc[i][j][2*p+1];
                    float n0 = b0m ? s0 + 1e-6f : __expf(s2.x);
                    float n1 = b1m ? s1 + 1e-6f : __expf(s2.y);
                    rsl[i][p] += (b0m ? s0 : 0.f) + (b1m ? s1 : 0.f);
                    *(float2*)&Ps[rr*68 + cl] = make_float2(to_tf32(n0), to_tf32(n1));
                }
            }
        }
        // loop-top sync publishes Ps
    }

    __syncthreads();   // Ps(31) visible
    // final PV(31), V parity 1
    {
        const float* Vb = Vts + 1*64*68;
        int rb = warp*16;
        #pragma unroll
        for (int k0 = 0; k0 < 64; k0 += 8) {
            float a[4], bf[8][2];
            a[0] = Ps[(rb+g  )*68 + k0+tg  ];
            a[1] = Ps[(rb+g+8)*68 + k0+tg  ];
            a[2] = Ps[(rb+g  )*68 + k0+tg+4];
            a[3] = Ps[(rb+g+8)*68 + k0+tg+4];
            #pragma unroll
            for (int j=0;j<8;j++) {
                bf[j][0] = Vb[(j*8+g)*68 + k0+tg  ];
                bf[j][1] = Vb[(j*8+g)*68 + k0+tg+4];
            }
            #pragma unroll
            for (int j=0;j<8;j++) mma_tf32(oacc[j], a, bf[j]);
        }
    }

    // masked row-sum reduction
    #pragma unroll
    for (int i=0;i<2;i++)
        #pragma unroll
        for (int p=0;p<2;p++) {
            float v = rsl[i][p];
            v += __shfl_xor_sync(0xffffffffu, v, 1);
            v += __shfl_xor_sync(0xffffffffu, v, 2);
            if (tg == 0) atomicAdd(&rowsum[wm*32 + i*16 + g + 8*p], v);
        }
    __syncthreads();

    const float* spb = sp_lse + (size_t)bh*S_ + m0;
    float* ob = outp + ((size_t)(b*S_ + m0))*D_ + h*DH_;
    int r0 = warp*16 + g;
    float den0 = 1.0f / (rowsum[r0  ] + 1e-6f + __expf(spb[r0  ]));
    float den1 = 1.0f / (rowsum[r0+8] + 1e-6f + __expf(spb[r0+8]));
    #pragma unroll
    for (int j=0;j<8;j++) {
        int cc = j*8 + 2*tg;
        *(float2*)&ob[(size_t)r0*D_ + cc] =
            make_float2(oacc[j][0]*den0, oacc[j][1]*den0);
        *(float2*)&ob[(size_t)(r0+8)*D_ + cc] =
            make_float2(oacc[j][2]*den1, oacc[j][3]*den1);
    }
}

// ---------------------------------------------------------------------------
extern "C" void kernel_launch(void* const* d_in, const int* in_sizes, int n_in,
                              void* d_out, int out_size) {
    (void)in_sizes; (void)n_in; (void)out_size;
    const float*   q    = (const float*)d_in[1];
    const float*   k    = (const float*)d_in[2];
    const float*   v    = (const float*)d_in[3];
    const void*    mask = d_in[4];
    const float*   sp   = (const float*)d_in[5];
    const float*   saw  = (const float*)d_in[6];
    const float*   Wq1  = (const float*)d_in[8];
    const float*   Wk1  = (const float*)d_in[9];
    const float*   Wq2  = (const float*)d_in[10];
    const float*   Wk2  = (const float*)d_in[11];
    const float*   Wint = (const float*)d_in[12];
    const float*   sD   = (const float*)d_in[13];
    const float*   sD2  = (const float*)d_in[14];
    float* outp = (float*)d_out;

    const int SMEMF = (128*68 + 64*68 + 64*68 + 128*68) * 4;               // 104448
    const int SMEMA = (128*36 + 2*64*36 + 2*64*68 + 128*68 + 128) * 4;     // 107008

    cudaFuncSetAttribute(fused_kernel, cudaFuncAttributeMaxDynamicSharedMemorySize, SMEMF);
    cudaFuncSetAttribute(attn_kernel,  cudaFuncAttributeMaxDynamicSharedMemorySize, SMEMA);

    detect_mask_kernel<<<1, 32>>>((const uint32_t*)mask);
    maskbits_kernel<<<1024, 256>>>(mask);
    vt_kernel<<<dim3(32, BH_), 256>>>(v);
    fused_kernel<<<dim3(16, BH_, 2), 256, SMEMF>>>(q, k, Wq1, Wk1, Wq2, Wk2, Wint, sD, sD2);
    attn_kernel<<<dim3(16, BH_), 256, SMEMA>>>(sp, saw, outp);
}

// round 9
// speedup vs baseline: 1.4681x; 1.4681x over previous
#include <cuda_runtime.h>
#include <cuda_bf16.h>
#include <cstdint>

#define B_    2
#define S_    2048
#define H_    16
#define DH_   64
#define DHID_ 256
#define DKER_ 64
#define D_    1024
#define BH_   (B_*H_)

// Scratch (static device globals)
__device__ uint32_t g_qf_w[BH_*S_*32];      // 8 MB  |qf| bf16x2
__device__ uint32_t g_kf_w[BH_*S_*32];      // 8 MB  |kf| bf16x2
__device__ float    g_vt  [BH_*64*S_];      // 16 MB V^T [bh][e][perm(s)], tf32-rounded
__device__ uint32_t g_maskbits[B_*S_*S_/32];

__device__ __forceinline__ float to_tf32(float x) {
    uint32_t u;
    asm("cvt.rna.tf32.f32 %0, %1;" : "=r"(u) : "f"(x));
    return __uint_as_float(u);
}
__device__ __forceinline__ uint32_t packbf(float lo, float hi) {
    uint32_t r;
    asm("cvt.rn.bf16x2.f32 %0, %1, %2;" : "=r"(r) : "f"(hi), "f"(lo));
    return r;
}
__device__ __forceinline__ float gelu_t(float x) {
    float x3 = x * x * x;
    float t  = tanhf(0.7978845608028654f * (x + 0.044715f * x3));
    return 0.5f * x * (1.0f + t);
}
__device__ __forceinline__ void mma_tf32(float* c, const float* a, const float* b) {
    asm volatile(
        "mma.sync.aligned.m16n8k8.row.col.f32.tf32.tf32.f32 "
        "{%0,%1,%2,%3}, {%4,%5,%6,%7}, {%8,%9}, {%0,%1,%2,%3};\n"
        : "+f"(c[0]), "+f"(c[1]), "+f"(c[2]), "+f"(c[3])
        : "r"(__float_as_uint(a[0])), "r"(__float_as_uint(a[1])),
          "r"(__float_as_uint(a[2])), "r"(__float_as_uint(a[3])),
          "r"(__float_as_uint(b[0])), "r"(__float_as_uint(b[1])));
}
__device__ __forceinline__ void mma_bf16(float* c, const uint32_t* a, uint32_t b0, uint32_t b1) {
    asm volatile(
        "mma.sync.aligned.m16n8k16.row.col.f32.bf16.bf16.f32 "
        "{%0,%1,%2,%3}, {%4,%5,%6,%7}, {%8,%9}, {%0,%1,%2,%3};\n"
        : "+f"(c[0]), "+f"(c[1]), "+f"(c[2]), "+f"(c[3])
        : "r"(a[0]), "r"(a[1]), "r"(a[2]), "r"(a[3]),
          "r"(b0), "r"(b1));
}
__device__ __forceinline__ void ldsm_x4(uint32_t* r, uint32_t addr) {
    asm volatile("ldmatrix.sync.aligned.m8n8.x4.shared.b16 {%0,%1,%2,%3}, [%4];"
        : "=r"(r[0]), "=r"(r[1]), "=r"(r[2]), "=r"(r[3]) : "r"(addr));
}
__device__ __forceinline__ uint32_t smaddr(const void* p) {
    return (uint32_t)__cvta_generic_to_shared(p);
}
#define CPA16(dst, src) \
    asm volatile("cp.async.cg.shared.global [%0], [%1], 16;\n" :: "r"(dst), "l"(src))
#define CPA_COMMIT() asm volatile("cp.async.commit_group;\n" ::: "memory")
#define CPA_WAIT(N)  asm volatile("cp.async.wait_group %0;\n" :: "n"(N) : "memory")

// ---------------------------------------------------------------------------
// Mask bit-pack with per-block dtype detection.
// Decode is `word != 0` for BOTH int32 and float32 encodings (0.0f is all-zero
// bits; 1.0f != 0), so only uint8-vs-wordsize must be detected: a uint8-packed
// word from 0/1 bytes is outside {0, 1, 0x3f800000} with overwhelming
// probability over the block's 2048-word window.
// ---------------------------------------------------------------------------
__global__ __launch_bounds__(256)
void maskbits_kernel(const void* __restrict__ m) {
    const uint32_t* w32 = (const uint32_t*)m;
    int tid = threadIdx.x;
    size_t wbase = (size_t)blockIdx.x * 2048;
    int flag = 0;
    #pragma unroll
    for (int u = 0; u < 8; u++) {
        uint32_t w = w32[wbase + tid*8 + u];
        if (w > 1u && w != 0x3f800000u) flag = 1;
    }
    int isb8 = __syncthreads_or(flag);

    int warpg = (blockIdx.x * 256 + tid) >> 5;
    int lane  = tid & 31;
    size_t base = (size_t)warpg * 1024;
    #pragma unroll 4
    for (int s = 0; s < 32; s++) {
        size_t idx = base + (size_t)s * 32 + lane;
        bool v = isb8 ? (((const uint8_t*)m)[idx] != 0) : (w32[idx] != 0u);
        unsigned w = __ballot_sync(0xffffffffu, v);
        if (lane == s) g_maskbits[base/32 + s] = w;
    }
}

// ---------------------------------------------------------------------------
// V transpose + tf32 pre-round + k-dim permute: g_vt[bh][e][perm(s)]
// perm within each 8-block: u -> ((u&3)<<1) | (u>>2)   (tg,tg+4 pairs adjacent)
// ---------------------------------------------------------------------------
__global__ __launch_bounds__(256)
void vt_kernel(const float* __restrict__ Vg) {
    __shared__ float ts[64][65];
    int bh = blockIdx.y, b = bh >> 4, h = bh & 15;
    int s0 = blockIdx.x * 64;
    int tid = threadIdx.x;
    const float* src = Vg + ((size_t)(b*S_ + s0))*D_ + h*DH_;
    for (int idx = tid; idx < 4096; idx += 256) {
        int r = idx >> 6, e = idx & 63;
        ts[e][r] = to_tf32(src[(size_t)r*D_ + e]);
    }
    __syncthreads();
    float* dst = g_vt + (size_t)bh*64*S_ + s0;
    for (int idx = tid; idx < 4096; idx += 256) {
        int e = idx >> 6, sl = idx & 63;
        int sp = (sl & ~7) | (((sl & 3) << 1) | ((sl >> 2) & 1));
        dst[(size_t)e*S_ + sp] = ts[e][sl];
    }
}

// ---------------------------------------------------------------------------
// Merged fused feature maps: blockIdx.z = 0 (q path) / 1 (k path)
// ---------------------------------------------------------------------------
__global__ __launch_bounds__(256, 2)
void fused_kernel(const float* __restrict__ Xq, const float* __restrict__ Xk,
                  const float* __restrict__ Wq1, const float* __restrict__ Wk1,
                  const float* __restrict__ Wq2, const float* __restrict__ Wk2,
                  const float* __restrict__ Wint,
                  const float* __restrict__ sD, const float* __restrict__ sD2)
{
    extern __shared__ float sm[];
    float* Xs  = sm;                  // 128*68
    float* W1s = Xs  + 128*68;        // 64*68
    float* W2s = W1s + 64*68;         // 64*68
    float* T1s = W2s + 64*68;         // 128*68

    bool kpath = (blockIdx.z != 0);
    const float* X  = kpath ? Xk  : Xq;
    const float* W1 = kpath ? Wk1 : Wq1;
    const float* W2 = kpath ? Wk2 : Wq2;
    uint32_t* outg  = kpath ? g_kf_w : g_qf_w;

    int bh = blockIdx.y, b = bh >> 4, h = bh & 15;
    int m0 = blockIdx.x * 128;
    int tid = threadIdx.x;
    int warp = tid >> 5, lane = tid & 31, g = lane >> 2, tg = lane & 3;
    int wm = warp & 3, wn = warp >> 2;

    const float* Xb = X + ((size_t)(b*S_ + m0))*D_ + h*DH_;
    for (int idx = tid; idx < 128*64; idx += 256) {
        int r = idx >> 6, d = idx & 63;
        Xs[r*68 + d] = to_tf32(Xb[(size_t)r*D_ + d]);
    }

    const float* W1h = W1 + (size_t)h*DH_*DHID_;
    const float* W2h = W2 + (size_t)h*DHID_*DKER_;

    float acc2[8][4];
    #pragma unroll
    for (int j=0;j<8;j++) for (int c=0;c<4;c++) acc2[j][c]=0.f;

    for (int c0 = 0; c0 < 4; c0++) {
        int n0 = c0*64;
        for (int idx = tid; idx < 64*64; idx += 256) {
            int k = idx >> 6, n = idx & 63;
            W1s[n*68 + k] = to_tf32(W1h[(size_t)k*DHID_ + n0 + n]);
        }
        __syncthreads();

        float acc1[2][4][4];
        #pragma unroll
        for (int i=0;i<2;i++) for (int j=0;j<4;j++) for (int c=0;c<4;c++) acc1[i][j][c]=0.f;
        #pragma unroll
        for (int k0=0;k0<64;k0+=8) {
            float a[2][4], bf[4][2];
            #pragma unroll
            for (int i=0;i<2;i++) {
                int rb = wm*32 + i*16;
                a[i][0] = Xs[(rb+g  )*68 + k0+tg  ];
                a[i][1] = Xs[(rb+g+8)*68 + k0+tg  ];
                a[i][2] = Xs[(rb+g  )*68 + k0+tg+4];
                a[i][3] = Xs[(rb+g+8)*68 + k0+tg+4];
            }
            #pragma unroll
            for (int j=0;j<4;j++) {
                int nb = wn*32 + j*8 + g;
                bf[j][0] = W1s[nb*68 + k0+tg  ];
                bf[j][1] = W1s[nb*68 + k0+tg+4];
            }
            #pragma unroll
            for (int i=0;i<2;i++)
                #pragma unroll
                for (int j=0;j<4;j++)
                    mma_tf32(acc1[i][j], a[i], bf[j]);
        }
        #pragma unroll
        for (int i=0;i<2;i++) {
            #pragma unroll
            for (int j=0;j<4;j++) {
                int rr = wm*32 + i*16 + g;
                int cc = wn*32 + j*8 + 2*tg;
                *(float2*)&T1s[rr*68 + cc] =
                    make_float2(to_tf32(gelu_t(acc1[i][j][0])), to_tf32(gelu_t(acc1[i][j][1])));
                *(float2*)&T1s[(rr+8)*68 + cc] =
                    make_float2(to_tf32(gelu_t(acc1[i][j][2])), to_tf32(gelu_t(acc1[i][j][3])));
            }
        }
        for (int idx = tid; idx < 64*64; idx += 256) {
            int k = idx >> 6, n = idx & 63;
            W2s[n*68 + k] = to_tf32(W2h[(size_t)(n0 + k)*DKER_ + n]);
        }
        __syncthreads();

        #pragma unroll
        for (int k0=0;k0<64;k0+=8) {
            float a[4], bf[8][2];
            int rb = warp*16;
            a[0] = T1s[(rb+g  )*68 + k0+tg  ];
            a[1] = T1s[(rb+g+8)*68 + k0+tg  ];
            a[2] = T1s[(rb+g  )*68 + k0+tg+4];
            a[3] = T1s[(rb+g+8)*68 + k0+tg+4];
            #pragma unroll
            for (int j=0;j<8;j++) {
                int nb = j*8+g;
                bf[j][0] = W2s[nb*68 + k0+tg  ];
                bf[j][1] = W2s[nb*68 + k0+tg+4];
            }
            #pragma unroll
            for (int j=0;j<8;j++) mma_tf32(acc2[j], a, bf[j]);
        }
    }

    uint32_t* outw = outg + ((size_t)bh*S_ + m0)*32;

    if (!kpath) {
        #pragma unroll
        for (int j=0;j<8;j++) {
            int rr = warp*16 + g, wi = j*4 + tg;
            outw[(size_t)rr*32 + wi] =
                packbf(fabsf(gelu_t(acc2[j][0])), fabsf(gelu_t(acc2[j][1])));
            outw[(size_t)(rr+8)*32 + wi] =
                packbf(fabsf(gelu_t(acc2[j][2])), fabsf(gelu_t(acc2[j][3])));
        }
        return;
    }

    const float* sDh  = sD  + h*DKER_;
    const float* sD2h = sD2 + h*DKER_;
    __syncthreads();
    #pragma unroll
    for (int j=0;j<8;j++) {
        int rr = warp*16 + g, cc = j*8 + 2*tg;
        T1s[rr*68 + cc  ]     = fabsf(sDh[cc  ]) * gelu_t(acc2[j][0]);
        T1s[rr*68 + cc+1]     = fabsf(sDh[cc+1]) * gelu_t(acc2[j][1]);
        T1s[(rr+8)*68 + cc  ] = fabsf(sDh[cc  ]) * gelu_t(acc2[j][2]);
        T1s[(rr+8)*68 + cc+1] = fabsf(sDh[cc+1]) * gelu_t(acc2[j][3]);
    }
    const float* Wih = Wint + (size_t)h*DKER_*DKER_;
    for (int idx = tid; idx < 64*64; idx += 256) {
        int k = idx >> 6, n = idx & 63;
        W1s[n*68 + k] = to_tf32(Wih[(size_t)k*DKER_ + n]);
    }
    __syncthreads();

    float ac2[8][4];
    #pragma unroll
    for (int j=0;j<8;j++) for (int c=0;c<4;c++) ac2[j][c]=0.f;
    #pragma unroll
    for (int k0=0;k0<64;k0+=8) {
        float a[4], bf[8][2];
        int rb = warp*16;
        a[0] = to_tf32(T1s[(rb+g  )*68 + k0+tg  ]);
        a[1] = to_tf32(T1s[(rb+g+8)*68 + k0+tg  ]);
        a[2] = to_tf32(T1s[(rb+g  )*68 + k0+tg+4]);
        a[3] = to_tf32(T1s[(rb+g+8)*68 + k0+tg+4]);
        #pragma unroll
        for (int j=0;j<8;j++) {
            int nb = j*8+g;
            bf[j][0] = W1s[nb*68 + k0+tg  ];
            bf[j][1] = W1s[nb*68 + k0+tg+4];
        }
        #pragma unroll
        for (int j=0;j<8;j++) mma_tf32(ac2[j], a, bf[j]);
    }

    #pragma unroll
    for (int j=0;j<8;j++) {
        int rr = warp*16 + g, cc = j*8 + 2*tg;
        int wi = j*4 + tg;
        float t00 = T1s[rr*68 + cc  ],     t01 = T1s[rr*68 + cc+1];
        float t10 = T1s[(rr+8)*68 + cc],   t11 = T1s[(rr+8)*68 + cc+1];
        outw[(size_t)rr*32 + wi] =
            packbf(fabsf(t00 + ac2[j][0]*sD2h[cc  ]),
                   fabsf(t01 + ac2[j][1]*sD2h[cc+1]));
        outw[(size_t)(rr+8)*32 + wi] =
            packbf(fabsf(t10 + ac2[j][2]*sD2h[cc  ]),
                   fabsf(t11 + ac2[j][3]*sD2h[cc+1]));
    }
}

// ---------------------------------------------------------------------------
// Attention: bf16 scores (ldmatrix), tf32 PV (permuted k-layout, LDS.64),
// saw via LDG in the epilogue. 2 syncthreads per tile.
// Per tile t (Ps = P(t-1), KV(t) pending):
//   WAIT(0)+sync -> PV(t-1) -> sync -> issue KV(t+1)
//   -> score MMA(t) -> [mem fence] epilogue: LDG saw/mask, compute, store Ps
// smem words: Qs[128*36] Ks[2*64*36] Vts[2*64*68] Ps[128*68] rowsum[128]
// = 107008 B -> 2 CTAs/SM
// ---------------------------------------------------------------------------
__global__ __launch_bounds__(256, 2)
void attn_kernel(const float* __restrict__ sp_lse, const float* __restrict__ saw,
                 float* __restrict__ outp) {
    extern __shared__ uint32_t smw[];
    uint32_t* Qs  = smw;                     // 128*36 (bf16x2)
    uint32_t* Ks  = Qs + 128*36;             // 2*64*36 (bf16x2)
    float*    Vts = (float*)(Ks + 2*64*36);  // 2*64*68 f32 (V^T tiles, perm cols)
    float*    Ps  = Vts + 2*64*68;           // 128*68 f32 (perm cols)
    float* rowsum = Ps + 128*68;             // 128

    int bh = blockIdx.y, b = bh >> 4, h = bh & 15;
    int m0 = blockIdx.x * 128;
    int tid = threadIdx.x, warp = tid>>5, lane = tid&31, g = lane>>2, tg = lane&3;
    int wm = warp & 3, wn = warp >> 2;
    int po0 = ((tg & 1) << 2) | (tg >> 1);   // perm storage offset of logical 2tg
    int po1 = po0 + 2;                       // perm storage offset of logical 2tg+1

    // Q tile (bf16 words)
    const uint32_t* qsrc = g_qf_w + ((size_t)bh*S_ + m0)*32;
    for (int idx = tid; idx < 4096; idx += 256) {
        int r = idx >> 5, c = idx & 31;
        Qs[r*36 + c] = qsrc[idx];
    }
    if (tid < 128) rowsum[tid] = 0.f;

    const char* kbase  = (const char*)(g_kf_w + (size_t)bh*S_*32);
    const char* vtbase = (const char*)(g_vt + (size_t)bh*64*S_);
    const float* sawb  = saw + (size_t)bh*S_*S_;

    // ldmatrix lane addressing
    int mrow = lane & 15;
    int mwo  = (lane >> 4) << 2;

    // prologue: KV(0)
    {
        #pragma unroll
        for (int c2 = 0; c2 < 2; c2++) {
            int qi = tid + c2*256, r = qi >> 3, cc = qi & 7;
            CPA16(smaddr(Ks + r*36) + cc*16, kbase + (size_t)r*128 + cc*16);
        }
        #pragma unroll
        for (int c2 = 0; c2 < 4; c2++) {
            int qi = tid + c2*256, r = qi >> 4, cc = qi & 15;
            CPA16(smaddr(Vts + r*68) + cc*16, vtbase + (size_t)r*(S_*4) + cc*16);
        }
        CPA_COMMIT();
    }

    float oacc[8][4];
    #pragma unroll
    for (int j=0;j<8;j++) for (int c=0;c<4;c++) oacc[j][c]=0.f;
    float rsl[2][2] = {{0.f,0.f},{0.f,0.f}};

    for (int t = 0; t < 32; t++) {
        int pt = t & 1;

        // (1) KV(t) ready; Ps = P(t-1) published
        CPA_WAIT(0);
        __syncthreads();

        // (2) PV(t-1): tf32, permuted layout -> LDS.64 fragments
        if (t > 0) {
            const float* Vb = Vts + (pt^1)*64*68;
            int rb = warp*16;
            #pragma unroll
            for (int k0 = 0; k0 < 64; k0 += 8) {
                float2 a01 = *(const float2*)&Ps[(rb+g  )*68 + k0 + 2*tg];
                float2 a23 = *(const float2*)&Ps[(rb+g+8)*68 + k0 + 2*tg];
                float a[4] = {a01.x, a23.x, a01.y, a23.y};
                float bf[8][2];
                #pragma unroll
                for (int j=0;j<8;j++) {
                    float2 b01 = *(const float2*)&Vb[(j*8+g)*68 + k0 + 2*tg];
                    bf[j][0] = b01.x; bf[j][1] = b01.y;
                }
                #pragma unroll
                for (int j=0;j<8;j++) mma_tf32(oacc[j], a, bf[j]);
            }
        }
        // (3) Ps / old KV buffers free
        __syncthreads();

        // (4) KV(t+1) cp.async into parity pt^1
        if (t < 31) {
            size_t t0n = (size_t)(t+1)*64;
            uint32_t* Kd = Ks  + (pt^1)*64*36;
            float*    Vd = Vts + (pt^1)*64*68;
            #pragma unroll
            for (int c2 = 0; c2 < 2; c2++) {
                int qi = tid + c2*256, r = qi >> 3, cc = qi & 7;
                CPA16(smaddr(Kd + r*36) + cc*16, kbase + (t0n + r)*128 + cc*16);
            }
            #pragma unroll
            for (int c2 = 0; c2 < 4; c2++) {
                int qi = tid + c2*256, r = qi >> 4, cc = qi & 15;
                CPA16(smaddr(Vd + r*68) + cc*16,
                      vtbase + (size_t)r*(S_*4) + t0n*4 + cc*16);
            }
        }
        CPA_COMMIT();

        // (5) score MMA(t): bf16 via ldmatrix
        float sacc[2][4][4];
        #pragma unroll
        for (int i=0;i<2;i++) for (int j=0;j<4;j++) for (int c=0;c<4;c++) sacc[i][j][c]=0.f;
        {
            const uint32_t* Kb = Ks + pt*64*36;
            uint32_t qa = smaddr(Qs + (wm*32 + mrow)*36 + mwo);
            uint32_t ka = smaddr(Kb + (wn*32 + mrow)*36 + mwo);
            #pragma unroll
            for (int kw = 0; kw < 32; kw += 8) {
                uint32_t a0[4], a1[4], b0[4], b1[4];
                ldsm_x4(a0, qa + kw*4);
                ldsm_x4(a1, qa + 16*36*4 + kw*4);
                ldsm_x4(b0, ka + kw*4);
                ldsm_x4(b1, ka + 16*36*4 + kw*4);
                mma_bf16(sacc[0][0], a0, b0[0], b0[2]);
                mma_bf16(sacc[0][1], a0, b0[1], b0[3]);
                mma_bf16(sacc[0][2], a0, b1[0], b1[2]);
                mma_bf16(sacc[0][3], a0, b1[1], b1[3]);
                mma_bf16(sacc[1][0], a1, b0[0], b0[2]);
                mma_bf16(sacc[1][1], a1, b0[1], b0[3]);
                mma_bf16(sacc[1][2], a1, b1[0], b1[2]);
                mma_bf16(sacc[1][3], a1, b1[1], b1[3]);
            }
        }

        // keep saw/mask LDGs from being hoisted above the MMA
        asm volatile("" ::: "memory");

        // (6) epilogue: LDG saw/mask, compute, store P(t) -> Ps (permuted cols)
        #pragma unroll
        for (int i=0;i<2;i++) {
            int rg0 = m0 + wm*32 + i*16 + g;
            uint32_t mwd[2];
            float2 sv[4][2];
            #pragma unroll
            for (int p=0;p<2;p++) {
                mwd[p] = g_maskbits[((size_t)(b*S_ + rg0 + 8*p))*64 + t*2 + wn];
                const float* srow = sawb + (size_t)(rg0 + 8*p)*S_ + t*64 + wn*32;
                #pragma unroll
                for (int j=0;j<4;j++)
                    sv[j][p] = *(const float2*)(srow + j*8 + 2*tg);
            }
            #pragma unroll
            for (int j=0;j<4;j++) {
                int basec = wn*32 + j*8;
                int bit = j*8 + 2*tg;
                #pragma unroll
                for (int p=0;p<2;p++) {
                    int rr = wm*32 + i*16 + g + 8*p;
                    float2 s2 = sv[j][p];
                    uint32_t word = mwd[p];
                    bool b0m = (word >> bit) & 1u;
                    bool b1m = (word >> (bit+1)) & 1u;
                    float s0 = sacc[i][j][2*p], s1 = sacc[i][j][2*p+1];
                    float n0 = b0m ? s0 + 1e-6f : __expf(s2.x);
                    float n1 = b1m ? s1 + 1e-6f : __expf(s2.y);
                    rsl[i][p] += (b0m ? s0 : 0.f) + (b1m ? s1 : 0.f);
                    Ps[rr*68 + basec + po0] = to_tf32(n0);
                    Ps[rr*68 + basec + po1] = to_tf32(n1);
                }
            }
        }
        // loop-top sync publishes Ps
    }

    __syncthreads();   // P(31) visible
    // final PV(31), V parity 1
    {
        const float* Vb = Vts + 1*64*68;
        int rb = warp*16;
        #pragma unroll
        for (int k0 = 0; k0 < 64; k0 += 8) {
            float2 a01 = *(const float2*)&Ps[(rb+g  )*68 + k0 + 2*tg];
            float2 a23 = *(const float2*)&Ps[(rb+g+8)*68 + k0 + 2*tg];
            float a[4] = {a01.x, a23.x, a01.y, a23.y};
            float bf[8][2];
            #pragma unroll
            for (int j=0;j<8;j++) {
                float2 b01 = *(const float2*)&Vb[(j*8+g)*68 + k0 + 2*tg];
                bf[j][0] = b01.x; bf[j][1] = b01.y;
            }
            #pragma unroll
            for (int j=0;j<8;j++) mma_tf32(oacc[j], a, bf[j]);
        }
    }

    // masked row-sum reduction
    #pragma unroll
    for (int i=0;i<2;i++)
        #pragma unroll
        for (int p=0;p<2;p++) {
            float v = rsl[i][p];
            v += __shfl_xor_sync(0xffffffffu, v, 1);
            v += __shfl_xor_sync(0xffffffffu, v, 2);
            if (tg == 0) atomicAdd(&rowsum[wm*32 + i*16 + g + 8*p], v);
        }
    __syncthreads();

    const float* spb = sp_lse + (size_t)bh*S_ + m0;
    float* ob = outp + ((size_t)(b*S_ + m0))*D_ + h*DH_;
    int r0 = warp*16 + g;
    float den0 = 1.0f / (rowsum[r0  ] + 1e-6f + __expf(spb[r0  ]));
    float den1 = 1.0f / (rowsum[r0+8] + 1e-6f + __expf(spb[r0+8]));
    #pragma unroll
    for (int j=0;j<8;j++) {
        int cc = j*8 + 2*tg;
        *(float2*)&ob[(size_t)r0*D_ + cc] =
            make_float2(oacc[j][0]*den0, oacc[j][1]*den0);
        *(float2*)&ob[(size_t)(r0+8)*D_ + cc] =
            make_float2(oacc[j][2]*den1, oacc[j][3]*den1);
    }
}

// ---------------------------------------------------------------------------
extern "C" void kernel_launch(void* const* d_in, const int* in_sizes, int n_in,
                              void* d_out, int out_size) {
    (void)in_sizes; (void)n_in; (void)out_size;
    const float*   q    = (const float*)d_in[1];
    const float*   k    = (const float*)d_in[2];
    const float*   v    = (const float*)d_in[3];
    const void*    mask = d_in[4];
    const float*   sp   = (const float*)d_in[5];
    const float*   saw  = (const float*)d_in[6];
    const float*   Wq1  = (const float*)d_in[8];
    const float*   Wk1  = (const float*)d_in[9];
    const float*   Wq2  = (const float*)d_in[10];
    const float*   Wk2  = (const float*)d_in[11];
    const float*   Wint = (const float*)d_in[12];
    const float*   sD   = (const float*)d_in[13];
    const float*   sD2  = (const float*)d_in[14];
    float* outp = (float*)d_out;

    const int SMEMF = (128*68 + 64*68 + 64*68 + 128*68) * 4;               // 104448
    const int SMEMA = (128*36 + 2*64*36 + 2*64*68 + 128*68 + 128) * 4;     // 107008

    cudaFuncSetAttribute(fused_kernel, cudaFuncAttributeMaxDynamicSharedMemorySize, SMEMF);
    cudaFuncSetAttribute(attn_kernel,  cudaFuncAttributeMaxDynamicSharedMemorySize, SMEMA);

    maskbits_kernel<<<1024, 256>>>(mask);
    vt_kernel<<<dim3(32, BH_), 256>>>(v);
    fused_kernel<<<dim3(16, BH_, 2), 256, SMEMF>>>(q, k, Wq1, Wk1, Wq2, Wk2, Wint, sD, sD2);
    attn_kernel<<<dim3(16, BH_), 256, SMEMA>>>(sp, saw, outp);
}

// round 10
// speedup vs baseline: 1.7359x; 1.1824x over previous
#include <cuda_runtime.h>
#include <cuda_bf16.h>
#include <cstdint>

#define B_    2
#define S_    2048
#define H_    16
#define DH_   64
#define DHID_ 256
#define DKER_ 64
#define D_    1024
#define BH_   (B_*H_)

// Scratch (static device globals)
__device__ uint32_t g_qf_w[BH_*S_*32];      // 8 MB  |qf| bf16x2
__device__ uint32_t g_kf_w[BH_*S_*32];      // 8 MB  |kf| bf16x2
__device__ float    g_vt  [BH_*64*S_];      // 16 MB V^T [bh][e][s], tf32-rounded
__device__ uint32_t g_maskbits[B_*S_*S_/32];

__device__ __forceinline__ float to_tf32(float x) {
    uint32_t u;
    asm("cvt.rna.tf32.f32 %0, %1;" : "=r"(u) : "f"(x));
    return __uint_as_float(u);
}
__device__ __forceinline__ uint32_t packbf(float lo, float hi) {
    uint32_t r;
    asm("cvt.rn.bf16x2.f32 %0, %1, %2;" : "=r"(r) : "f"(hi), "f"(lo));
    return r;
}
__device__ __forceinline__ float gelu_t(float x) {
    float x3 = x * x * x;
    float t  = tanhf(0.7978845608028654f * (x + 0.044715f * x3));
    return 0.5f * x * (1.0f + t);
}
__device__ __forceinline__ void mma_tf32(float* c, const float* a, const float* b) {
    asm volatile(
        "mma.sync.aligned.m16n8k8.row.col.f32.tf32.tf32.f32 "
        "{%0,%1,%2,%3}, {%4,%5,%6,%7}, {%8,%9}, {%0,%1,%2,%3};\n"
        : "+f"(c[0]), "+f"(c[1]), "+f"(c[2]), "+f"(c[3])
        : "r"(__float_as_uint(a[0])), "r"(__float_as_uint(a[1])),
          "r"(__float_as_uint(a[2])), "r"(__float_as_uint(a[3])),
          "r"(__float_as_uint(b[0])), "r"(__float_as_uint(b[1])));
}
__device__ __forceinline__ void mma_bf16(float* c, const uint32_t* a, uint32_t b0, uint32_t b1) {
    asm volatile(
        "mma.sync.aligned.m16n8k16.row.col.f32.bf16.bf16.f32 "
        "{%0,%1,%2,%3}, {%4,%5,%6,%7}, {%8,%9}, {%0,%1,%2,%3};\n"
        : "+f"(c[0]), "+f"(c[1]), "+f"(c[2]), "+f"(c[3])
        : "r"(a[0]), "r"(a[1]), "r"(a[2]), "r"(a[3]),
          "r"(b0), "r"(b1));
}
__device__ __forceinline__ void ldsm_x4(uint32_t* r, uint32_t addr) {
    asm volatile("ldmatrix.sync.aligned.m8n8.x4.shared.b16 {%0,%1,%2,%3}, [%4];"
        : "=r"(r[0]), "=r"(r[1]), "=r"(r[2]), "=r"(r[3]) : "r"(addr));
}
__device__ __forceinline__ uint32_t smaddr(const void* p) {
    return (uint32_t)__cvta_generic_to_shared(p);
}
#define CPA16(dst, src) \
    asm volatile("cp.async.cg.shared.global [%0], [%1], 16;\n" :: "r"(dst), "l"(src))
#define CPA_COMMIT() asm volatile("cp.async.commit_group;\n" ::: "memory")
#define CPA_WAIT(N)  asm volatile("cp.async.wait_group %0;\n" :: "n"(N) : "memory")

// ---------------------------------------------------------------------------
// Mask bit-pack with per-block dtype detection (word!=0 decodes both int32
// and float32; only uint8-vs-word must be detected).
// ---------------------------------------------------------------------------
__global__ __launch_bounds__(256)
void maskbits_kernel(const void* __restrict__ m) {
    const uint32_t* w32 = (const uint32_t*)m;
    int tid = threadIdx.x;
    size_t wbase = (size_t)blockIdx.x * 2048;
    int flag = 0;
    #pragma unroll
    for (int u = 0; u < 8; u++) {
        uint32_t w = w32[wbase + tid*8 + u];
        if (w > 1u && w != 0x3f800000u) flag = 1;
    }
    int isb8 = __syncthreads_or(flag);

    int warpg = (blockIdx.x * 256 + tid) >> 5;
    int lane  = tid & 31;
    size_t base = (size_t)warpg * 1024;
    #pragma unroll 4
    for (int s = 0; s < 32; s++) {
        size_t idx = base + (size_t)s * 32 + lane;
        bool v = isb8 ? (((const uint8_t*)m)[idx] != 0) : (w32[idx] != 0u);
        unsigned w = __ballot_sync(0xffffffffu, v);
        if (lane == s) g_maskbits[base/32 + s] = w;
    }
}

// ---------------------------------------------------------------------------
// V transpose + tf32 pre-round: g_vt[bh][e][s]  (no permutation)
// ---------------------------------------------------------------------------
__global__ __launch_bounds__(256)
void vt_kernel(const float* __restrict__ Vg) {
    __shared__ float ts[64][65];
    int bh = blockIdx.y, b = bh >> 4, h = bh & 15;
    int s0 = blockIdx.x * 64;
    int tid = threadIdx.x;
    const float* src = Vg + ((size_t)(b*S_ + s0))*D_ + h*DH_;
    for (int idx = tid; idx < 4096; idx += 256) {
        int r = idx >> 6, e = idx & 63;
        ts[e][r] = to_tf32(src[(size_t)r*D_ + e]);
    }
    __syncthreads();
    float* dst = g_vt + (size_t)bh*64*S_ + s0;
    for (int idx = tid; idx < 4096; idx += 256) {
        int e = idx >> 6, sl = idx & 63;
        dst[(size_t)e*S_ + sl] = ts[e][sl];
    }
}

// ---------------------------------------------------------------------------
// Merged fused feature maps: blockIdx.z = 0 (q path) / 1 (k path)
// ---------------------------------------------------------------------------
__global__ __launch_bounds__(256, 2)
void fused_kernel(const float* __restrict__ Xq, const float* __restrict__ Xk,
                  const float* __restrict__ Wq1, const float* __restrict__ Wk1,
                  const float* __restrict__ Wq2, const float* __restrict__ Wk2,
                  const float* __restrict__ Wint,
                  const float* __restrict__ sD, const float* __restrict__ sD2)
{
    extern __shared__ float sm[];
    float* Xs  = sm;                  // 128*68
    float* W1s = Xs  + 128*68;        // 64*68
    float* W2s = W1s + 64*68;         // 64*68
    float* T1s = W2s + 64*68;         // 128*68

    bool kpath = (blockIdx.z != 0);
    const float* X  = kpath ? Xk  : Xq;
    const float* W1 = kpath ? Wk1 : Wq1;
    const float* W2 = kpath ? Wk2 : Wq2;
    uint32_t* outg  = kpath ? g_kf_w : g_qf_w;

    int bh = blockIdx.y, b = bh >> 4, h = bh & 15;
    int m0 = blockIdx.x * 128;
    int tid = threadIdx.x;
    int warp = tid >> 5, lane = tid & 31, g = lane >> 2, tg = lane & 3;
    int wm = warp & 3, wn = warp >> 2;

    const float* Xb = X + ((size_t)(b*S_ + m0))*D_ + h*DH_;
    for (int idx = tid; idx < 128*64; idx += 256) {
        int r = idx >> 6, d = idx & 63;
        Xs[r*68 + d] = to_tf32(Xb[(size_t)r*D_ + d]);
    }

    const float* W1h = W1 + (size_t)h*DH_*DHID_;
    const float* W2h = W2 + (size_t)h*DHID_*DKER_;

    float acc2[8][4];
    #pragma unroll
    for (int j=0;j<8;j++) for (int c=0;c<4;c++) acc2[j][c]=0.f;

    for (int c0 = 0; c0 < 4; c0++) {
        int n0 = c0*64;
        for (int idx = tid; idx < 64*64; idx += 256) {
            int k = idx >> 6, n = idx & 63;
            W1s[n*68 + k] = to_tf32(W1h[(size_t)k*DHID_ + n0 + n]);
        }
        __syncthreads();

        float acc1[2][4][4];
        #pragma unroll
        for (int i=0;i<2;i++) for (int j=0;j<4;j++) for (int c=0;c<4;c++) acc1[i][j][c]=0.f;
        #pragma unroll
        for (int k0=0;k0<64;k0+=8) {
            float a[2][4], bf[4][2];
            #pragma unroll
            for (int i=0;i<2;i++) {
                int rb = wm*32 + i*16;
                a[i][0] = Xs[(rb+g  )*68 + k0+tg  ];
                a[i][1] = Xs[(rb+g+8)*68 + k0+tg  ];
                a[i][2] = Xs[(rb+g  )*68 + k0+tg+4];
                a[i][3] = Xs[(rb+g+8)*68 + k0+tg+4];
            }
            #pragma unroll
            for (int j=0;j<4;j++) {
                int nb = wn*32 + j*8 + g;
                bf[j][0] = W1s[nb*68 + k0+tg  ];
                bf[j][1] = W1s[nb*68 + k0+tg+4];
            }
            #pragma unroll
            for (int i=0;i<2;i++)
                #pragma unroll
                for (int j=0;j<4;j++)
                    mma_tf32(acc1[i][j], a[i], bf[j]);
        }
        #pragma unroll
        for (int i=0;i<2;i++) {
            #pragma unroll
            for (int j=0;j<4;j++) {
                int rr = wm*32 + i*16 + g;
                int cc = wn*32 + j*8 + 2*tg;
                *(float2*)&T1s[rr*68 + cc] =
                    make_float2(to_tf32(gelu_t(acc1[i][j][0])), to_tf32(gelu_t(acc1[i][j][1])));
                *(float2*)&T1s[(rr+8)*68 + cc] =
                    make_float2(to_tf32(gelu_t(acc1[i][j][2])), to_tf32(gelu_t(acc1[i][j][3])));
            }
        }
        for (int idx = tid; idx < 64*64; idx += 256) {
            int k = idx >> 6, n = idx & 63;
            W2s[n*68 + k] = to_tf32(W2h[(size_t)(n0 + k)*DKER_ + n]);
        }
        __syncthreads();

        #pragma unroll
        for (int k0=0;k0<64;k0+=8) {
            float a[4], bf[8][2];
            int rb = warp*16;
            a[0] = T1s[(rb+g  )*68 + k0+tg  ];
            a[1] = T1s[(rb+g+8)*68 + k0+tg  ];
            a[2] = T1s[(rb+g  )*68 + k0+tg+4];
            a[3] = T1s[(rb+g+8)*68 + k0+tg+4];
            #pragma unroll
            for (int j=0;j<8;j++) {
                int nb = j*8+g;
                bf[j][0] = W2s[nb*68 + k0+tg  ];
                bf[j][1] = W2s[nb*68 + k0+tg+4];
            }
            #pragma unroll
            for (int j=0;j<8;j++) mma_tf32(acc2[j], a, bf[j]);
        }
    }

    uint32_t* outw = outg + ((size_t)bh*S_ + m0)*32;

    if (!kpath) {
        #pragma unroll
        for (int j=0;j<8;j++) {
            int rr = warp*16 + g, wi = j*4 + tg;
            outw[(size_t)rr*32 + wi] =
                packbf(fabsf(gelu_t(acc2[j][0])), fabsf(gelu_t(acc2[j][1])));
            outw[(size_t)(rr+8)*32 + wi] =
                packbf(fabsf(gelu_t(acc2[j][2])), fabsf(gelu_t(acc2[j][3])));
        }
        return;
    }

    const float* sDh  = sD  + h*DKER_;
    const float* sD2h = sD2 + h*DKER_;
    __syncthreads();
    #pragma unroll
    for (int j=0;j<8;j++) {
        int rr = warp*16 + g, cc = j*8 + 2*tg;
        T1s[rr*68 + cc  ]     = fabsf(sDh[cc  ]) * gelu_t(acc2[j][0]);
        T1s[rr*68 + cc+1]     = fabsf(sDh[cc+1]) * gelu_t(acc2[j][1]);
        T1s[(rr+8)*68 + cc  ] = fabsf(sDh[cc  ]) * gelu_t(acc2[j][2]);
        T1s[(rr+8)*68 + cc+1] = fabsf(sDh[cc+1]) * gelu_t(acc2[j][3]);
    }
    const float* Wih = Wint + (size_t)h*DKER_*DKER_;
    for (int idx = tid; idx < 64*64; idx += 256) {
        int k = idx >> 6, n = idx & 63;
        W1s[n*68 + k] = to_tf32(Wih[(size_t)k*DKER_ + n]);
    }
    __syncthreads();

    float ac2[8][4];
    #pragma unroll
    for (int j=0;j<8;j++) for (int c=0;c<4;c++) ac2[j][c]=0.f;
    #pragma unroll
    for (int k0=0;k0<64;k0+=8) {
        float a[4], bf[8][2];
        int rb = warp*16;
        a[0] = to_tf32(T1s[(rb+g  )*68 + k0+tg  ]);
        a[1] = to_tf32(T1s[(rb+g+8)*68 + k0+tg  ]);
        a[2] = to_tf32(T1s[(rb+g  )*68 + k0+tg+4]);
        a[3] = to_tf32(T1s[(rb+g+8)*68 + k0+tg+4]);
        #pragma unroll
        for (int j=0;j<8;j++) {
            int nb = j*8+g;
            bf[j][0] = W1s[nb*68 + k0+tg  ];
            bf[j][1] = W1s[nb*68 + k0+tg+4];
        }
        #pragma unroll
        for (int j=0;j<8;j++) mma_tf32(ac2[j], a, bf[j]);
    }

    #pragma unroll
    for (int j=0;j<8;j++) {
        int rr = warp*16 + g, cc = j*8 + 2*tg;
        int wi = j*4 + tg;
        float t00 = T1s[rr*68 + cc  ],     t01 = T1s[rr*68 + cc+1];
        float t10 = T1s[(rr+8)*68 + cc],   t11 = T1s[(rr+8)*68 + cc+1];
        outw[(size_t)rr*32 + wi] =
            packbf(fabsf(t00 + ac2[j][0]*sD2h[cc  ]),
                   fabsf(t01 + ac2[j][1]*sD2h[cc+1]));
        outw[(size_t)(rr+8)*32 + wi] =
            packbf(fabsf(t10 + ac2[j][2]*sD2h[cc  ]),
                   fabsf(t11 + ac2[j][3]*sD2h[cc+1]));
    }
}

// ---------------------------------------------------------------------------
// Attention: bf16 scores (warp = 16 rows x ALL 64 cols), P stays in registers,
// tf32 PV feeding score C-fragments directly as A-fragments.
// ONE __syncthreads per tile. No Ps buffer, no atomics.
// Per tile t (KV(t) group pending at loop top):
//   WAIT(0) -> sync -> issue KV(t+1) -> score MMA(t) -> fence
//   -> epilogue (LDG saw/mask, transform sacc in place) -> PV(t) from regs
// smem: Qs[128*36]w Ks[2*64*36]w Vts[2*64*68]f = 72064 B -> 2 CTAs/SM
// ---------------------------------------------------------------------------
__global__ __launch_bounds__(256, 2)
void attn_kernel(const float* __restrict__ sp_lse, const float* __restrict__ saw,
                 float* __restrict__ outp) {
    extern __shared__ uint32_t smw[];
    uint32_t* Qs  = smw;                     // 128*36 (bf16x2)
    uint32_t* Ks  = Qs + 128*36;             // 2*64*36 (bf16x2)
    float*    Vts = (float*)(Ks + 2*64*36);  // 2*64*68 f32 (V^T tiles [e][t])

    int bh = blockIdx.y, b = bh >> 4, h = bh & 15;
    int m0 = blockIdx.x * 128;
    int tid = threadIdx.x, warp = tid>>5, lane = tid&31, g = lane>>2, tg = lane&3;

    // Q tile (bf16 words)
    const uint32_t* qsrc = g_qf_w + ((size_t)bh*S_ + m0)*32;
    for (int idx = tid; idx < 4096; idx += 256) {
        int r = idx >> 5, c = idx & 31;
        Qs[r*36 + c] = qsrc[idx];
    }

    const char* kbase  = (const char*)(g_kf_w + (size_t)bh*S_*32);
    const char* vtbase = (const char*)(g_vt + (size_t)bh*64*S_);
    const float* sawb  = saw + (size_t)bh*S_*S_;

    // ldmatrix lane addressing
    int mrow = lane & 15;
    int mwo  = (lane >> 4) << 2;

    // prologue: KV(0)
    {
        #pragma unroll
        for (int c2 = 0; c2 < 2; c2++) {
            int qi = tid + c2*256, r = qi >> 3, cc = qi & 7;
            CPA16(smaddr(Ks + r*36) + cc*16, kbase + (size_t)r*128 + cc*16);
        }
        #pragma unroll
        for (int c2 = 0; c2 < 4; c2++) {
            int qi = tid + c2*256, r = qi >> 4, cc = qi & 15;
            CPA16(smaddr(Vts + r*68) + cc*16, vtbase + (size_t)r*(S_*4) + cc*16);
        }
        CPA_COMMIT();
    }

    float oacc[8][4];
    #pragma unroll
    for (int j=0;j<8;j++) for (int c=0;c<4;c++) oacc[j][c]=0.f;
    float rsl[2] = {0.f, 0.f};

    int rg0 = m0 + warp*16 + g;   // this thread's first row

    for (int t = 0; t < 32; t++) {
        int pt = t & 1;

        // (1) KV(t) ready (per-warp wait), then barrier
        CPA_WAIT(0);
        __syncthreads();

        // (2) KV(t+1) cp.async into parity pt^1 (read only by tile t-1, done)
        if (t < 31) {
            size_t t0n = (size_t)(t+1)*64;
            uint32_t* Kd = Ks  + (pt^1)*64*36;
            float*    Vd = Vts + (pt^1)*64*68;
            #pragma unroll
            for (int c2 = 0; c2 < 2; c2++) {
                int qi = tid + c2*256, r = qi >> 3, cc = qi & 7;
                CPA16(smaddr(Kd + r*36) + cc*16, kbase + (t0n + r)*128 + cc*16);
            }
            #pragma unroll
            for (int c2 = 0; c2 < 4; c2++) {
                int qi = tid + c2*256, r = qi >> 4, cc = qi & 15;
                CPA16(smaddr(Vd + r*68) + cc*16,
                      vtbase + (size_t)r*(S_*4) + t0n*4 + cc*16);
            }
        }
        CPA_COMMIT();

        // (3) score MMA(t): warp computes rows 16w..16w+15 x all 64 cols
        float sacc[8][4];
        #pragma unroll
        for (int j=0;j<8;j++) for (int c=0;c<4;c++) sacc[j][c]=0.f;
        {
            const uint32_t* Kb = Ks + pt*64*36;
            uint32_t qa = smaddr(Qs + (warp*16 + mrow)*36 + mwo);
            uint32_t ka = smaddr(Kb + mrow*36 + mwo);
            #pragma unroll
            for (int kw = 0; kw < 32; kw += 8) {
                uint32_t av[4], bv[4][4];
                ldsm_x4(av, qa + kw*4);
                #pragma unroll
                for (int c = 0; c < 4; c++)
                    ldsm_x4(bv[c], ka + c*(16*36*4) + kw*4);
                #pragma unroll
                for (int j = 0; j < 8; j++)
                    mma_bf16(sacc[j], av, bv[j>>1][j&1], bv[j>>1][(j&1)+2]);
            }
        }

        // keep epilogue LDGs from hoisting above the MMA
        asm volatile("" ::: "memory");

        // (4) epilogue: transform sacc in place (two halves to bound regs)
        uint32_t mwd[2][2];
        #pragma unroll
        for (int p=0;p<2;p++) {
            mwd[p][0] = g_maskbits[((size_t)(b*S_ + rg0 + 8*p))*64 + t*2    ];
            mwd[p][1] = g_maskbits[((size_t)(b*S_ + rg0 + 8*p))*64 + t*2 + 1];
        }
        #pragma unroll
        for (int jh = 0; jh < 2; jh++) {
            float2 sv[4][2];
            #pragma unroll
            for (int p=0;p<2;p++) {
                const float* srow = sawb + (size_t)(rg0 + 8*p)*S_ + t*64 + jh*32;
                #pragma unroll
                for (int jj=0;jj<4;jj++)
                    sv[jj][p] = *(const float2*)(srow + jj*8 + 2*tg);
            }
            #pragma unroll
            for (int jj=0;jj<4;jj++) {
                int j = jh*4 + jj;
                int bit = jj*8 + 2*tg;
                #pragma unroll
                for (int p=0;p<2;p++) {
                    uint32_t word = mwd[p][jh];
                    bool b0m = (word >> bit) & 1u;
                    bool b1m = (word >> (bit+1)) & 1u;
                    float s0 = sacc[j][2*p], s1 = sacc[j][2*p+1];
                    float n0 = b0m ? s0 + 1e-6f : __expf(sv[jj][p].x);
                    float n1 = b1m ? s1 + 1e-6f : __expf(sv[jj][p].y);
                    rsl[p] += (b0m ? s0 : 0.f) + (b1m ? s1 : 0.f);
                    sacc[j][2*p]   = to_tf32(n0);
                    sacc[j][2*p+1] = to_tf32(n1);
                }
            }
        }

        // (5) PV(t): P from registers (C-frag -> A-frag reorder), V^T from smem
        {
            const float* Vb = Vts + pt*64*68;
            #pragma unroll
            for (int j = 0; j < 8; j++) {
                float a[4] = {sacc[j][0], sacc[j][2], sacc[j][1], sacc[j][3]};
                #pragma unroll
                for (int ng = 0; ng < 8; ng++) {
                    float2 b2 = *(const float2*)&Vb[(ng*8+g)*68 + j*8 + 2*tg];
                    float bf[2] = {b2.x, b2.y};
                    mma_tf32(oacc[ng], a, bf);
                }
            }
        }
    }

    // row sums: quad butterfly over tg (lane bits 0-1) -> every lane has sum
    #pragma unroll
    for (int p=0;p<2;p++) {
        rsl[p] += __shfl_xor_sync(0xffffffffu, rsl[p], 1);
        rsl[p] += __shfl_xor_sync(0xffffffffu, rsl[p], 2);
    }

    const float* spb = sp_lse + (size_t)bh*S_ + m0;
    float* ob = outp + ((size_t)(b*S_ + m0))*D_ + h*DH_;
    int r0 = warp*16 + g;
    float den0 = 1.0f / (rsl[0] + 1e-6f + __expf(spb[r0  ]));
    float den1 = 1.0f / (rsl[1] + 1e-6f + __expf(spb[r0+8]));
    #pragma unroll
    for (int j=0;j<8;j++) {
        int cc = j*8 + 2*tg;
        *(float2*)&ob[(size_t)r0*D_ + cc] =
            make_float2(oacc[j][0]*den0, oacc[j][1]*den0);
        *(float2*)&ob[(size_t)(r0+8)*D_ + cc] =
            make_float2(oacc[j][2]*den1, oacc[j][3]*den1);
    }
}

// ---------------------------------------------------------------------------
extern "C" void kernel_launch(void* const* d_in, const int* in_sizes, int n_in,
                              void* d_out, int out_size) {
    (void)in_sizes; (void)n_in; (void)out_size;
    const float*   q    = (const float*)d_in[1];
    const float*   k    = (const float*)d_in[2];
    const float*   v    = (const float*)d_in[3];
    const void*    mask = d_in[4];
    const float*   sp   = (const float*)d_in[5];
    const float*   saw  = (const float*)d_in[6];
    const float*   Wq1  = (const float*)d_in[8];
    const float*   Wk1  = (const float*)d_in[9];
    const float*   Wq2  = (const float*)d_in[10];
    const float*   Wk2  = (const float*)d_in[11];
    const float*   Wint = (const float*)d_in[12];
    const float*   sD   = (const float*)d_in[13];
    const float*   sD2  = (const float*)d_in[14];
    float* outp = (float*)d_out;

    const int SMEMF = (128*68 + 64*68 + 64*68 + 128*68) * 4;         // 104448
    const int SMEMA = (128*36 + 2*64*36 + 2*64*68) * 4;              // 71680

    cudaFuncSetAttribute(fused_kernel, cudaFuncAttributeMaxDynamicSharedMemorySize, SMEMF);
    cudaFuncSetAttribute(attn_kernel,  cudaFuncAttributeMaxDynamicSharedMemorySize, SMEMA);

    maskbits_kernel<<<1024, 256>>>(mask);
    vt_kernel<<<dim3(32, BH_), 256>>>(v);
    fused_kernel<<<dim3(16, BH_, 2), 256, SMEMF>>>(q, k, Wq1, Wk1, Wq2, Wk2, Wint, sD, sD2);
    attn_kernel<<<dim3(16, BH_), 256, SMEMA>>>(sp, saw, outp);
}

// round 11
// speedup vs baseline: 1.8877x; 1.0874x over previous
#include <cuda_runtime.h>
#include <cuda_bf16.h>
#include <cstdint>

#define B_    2
#define S_    2048
#define H_    16
#define DH_   64
#define DHID_ 256
#define DKER_ 64
#define D_    1024
#define BH_   (B_*H_)

// Scratch (static device globals)
__device__ uint32_t g_qf_w[BH_*S_*32];      // 8 MB  |qf| bf16x2
__device__ uint32_t g_kf_w[BH_*S_*32];      // 8 MB  |kf| bf16x2
__device__ float    g_vt  [BH_*64*S_];      // 16 MB V^T [bh][e][s], tf32-rounded
__device__ uint32_t g_maskbits[B_*S_*S_/32];

__device__ __forceinline__ float to_tf32(float x) {
    uint32_t u;
    asm("cvt.rna.tf32.f32 %0, %1;" : "=r"(u) : "f"(x));
    return __uint_as_float(u);
}
__device__ __forceinline__ uint32_t packbf(float lo, float hi) {
    uint32_t r;
    asm("cvt.rn.bf16x2.f32 %0, %1, %2;" : "=r"(r) : "f"(hi), "f"(lo));
    return r;
}
__device__ __forceinline__ float gelu_t(float x) {
    float x3 = x * x * x;
    float t  = tanhf(0.7978845608028654f * (x + 0.044715f * x3));
    return 0.5f * x * (1.0f + t);
}
__device__ __forceinline__ void mma_tf32(float* c, const float* a, const float* b) {
    asm volatile(
        "mma.sync.aligned.m16n8k8.row.col.f32.tf32.tf32.f32 "
        "{%0,%1,%2,%3}, {%4,%5,%6,%7}, {%8,%9}, {%0,%1,%2,%3};\n"
        : "+f"(c[0]), "+f"(c[1]), "+f"(c[2]), "+f"(c[3])
        : "r"(__float_as_uint(a[0])), "r"(__float_as_uint(a[1])),
          "r"(__float_as_uint(a[2])), "r"(__float_as_uint(a[3])),
          "r"(__float_as_uint(b[0])), "r"(__float_as_uint(b[1])));
}
__device__ __forceinline__ void mma_bf16(float* c, const uint32_t* a, uint32_t b0, uint32_t b1) {
    asm volatile(
        "mma.sync.aligned.m16n8k16.row.col.f32.bf16.bf16.f32 "
        "{%0,%1,%2,%3}, {%4,%5,%6,%7}, {%8,%9}, {%0,%1,%2,%3};\n"
        : "+f"(c[0]), "+f"(c[1]), "+f"(c[2]), "+f"(c[3])
        : "r"(a[0]), "r"(a[1]), "r"(a[2]), "r"(a[3]),
          "r"(b0), "r"(b1));
}
__device__ __forceinline__ void ldsm_x4(uint32_t* r, uint32_t addr) {
    asm volatile("ldmatrix.sync.aligned.m8n8.x4.shared.b16 {%0,%1,%2,%3}, [%4];"
        : "=r"(r[0]), "=r"(r[1]), "=r"(r[2]), "=r"(r[3]) : "r"(addr));
}
__device__ __forceinline__ uint32_t smaddr(const void* p) {
    return (uint32_t)__cvta_generic_to_shared(p);
}
#define CPA16(dst, src) \
    asm volatile("cp.async.cg.shared.global [%0], [%1], 16;\n" :: "r"(dst), "l"(src))
#define CPA_COMMIT() asm volatile("cp.async.commit_group;\n" ::: "memory")
#define CPA_WAIT(N)  asm volatile("cp.async.wait_group %0;\n" :: "n"(N) : "memory")

// ---------------------------------------------------------------------------
// Mask bit-pack with per-block dtype detection (word!=0 decodes both int32
// and float32; only uint8-vs-word must be detected).
// ---------------------------------------------------------------------------
__global__ __launch_bounds__(256)
void maskbits_kernel(const void* __restrict__ m) {
    const uint32_t* w32 = (const uint32_t*)m;
    int tid = threadIdx.x;
    size_t wbase = (size_t)blockIdx.x * 2048;
    int flag = 0;
    #pragma unroll
    for (int u = 0; u < 8; u++) {
        uint32_t w = w32[wbase + tid*8 + u];
        if (w > 1u && w != 0x3f800000u) flag = 1;
    }
    int isb8 = __syncthreads_or(flag);

    int warpg = (blockIdx.x * 256 + tid) >> 5;
    int lane  = tid & 31;
    size_t base = (size_t)warpg * 1024;
    #pragma unroll 4
    for (int s = 0; s < 32; s++) {
        size_t idx = base + (size_t)s * 32 + lane;
        bool v = isb8 ? (((const uint8_t*)m)[idx] != 0) : (w32[idx] != 0u);
        unsigned w = __ballot_sync(0xffffffffu, v);
        if (lane == s) g_maskbits[base/32 + s] = w;
    }
}

// ---------------------------------------------------------------------------
// V transpose + tf32 pre-round: g_vt[bh][e][s]
// ---------------------------------------------------------------------------
__global__ __launch_bounds__(256)
void vt_kernel(const float* __restrict__ Vg) {
    __shared__ float ts[64][65];
    int bh = blockIdx.y, b = bh >> 4, h = bh & 15;
    int s0 = blockIdx.x * 64;
    int tid = threadIdx.x;
    const float* src = Vg + ((size_t)(b*S_ + s0))*D_ + h*DH_;
    for (int idx = tid; idx < 4096; idx += 256) {
        int r = idx >> 6, e = idx & 63;
        ts[e][r] = to_tf32(src[(size_t)r*D_ + e]);
    }
    __syncthreads();
    float* dst = g_vt + (size_t)bh*64*S_ + s0;
    for (int idx = tid; idx < 4096; idx += 256) {
        int e = idx >> 6, sl = idx & 63;
        dst[(size_t)e*S_ + sl] = ts[e][sl];
    }
}

// ---------------------------------------------------------------------------
// Merged fused feature maps: blockIdx.z = 0 (q path) / 1 (k path)
// ---------------------------------------------------------------------------
__global__ __launch_bounds__(256, 2)
void fused_kernel(const float* __restrict__ Xq, const float* __restrict__ Xk,
                  const float* __restrict__ Wq1, const float* __restrict__ Wk1,
                  const float* __restrict__ Wq2, const float* __restrict__ Wk2,
                  const float* __restrict__ Wint,
                  const float* __restrict__ sD, const float* __restrict__ sD2)
{
    extern __shared__ float sm[];
    float* Xs  = sm;                  // 128*68
    float* W1s = Xs  + 128*68;        // 64*68
    float* W2s = W1s + 64*68;         // 64*68
    float* T1s = W2s + 64*68;         // 128*68

    bool kpath = (blockIdx.z != 0);
    const float* X  = kpath ? Xk  : Xq;
    const float* W1 = kpath ? Wk1 : Wq1;
    const float* W2 = kpath ? Wk2 : Wq2;
    uint32_t* outg  = kpath ? g_kf_w : g_qf_w;

    int bh = blockIdx.y, b = bh >> 4, h = bh & 15;
    int m0 = blockIdx.x * 128;
    int tid = threadIdx.x;
    int warp = tid >> 5, lane = tid & 31, g = lane >> 2, tg = lane & 3;
    int wm = warp & 3, wn = warp >> 2;

    const float* Xb = X + ((size_t)(b*S_ + m0))*D_ + h*DH_;
    for (int idx = tid; idx < 128*64; idx += 256) {
        int r = idx >> 6, d = idx & 63;
        Xs[r*68 + d] = to_tf32(Xb[(size_t)r*D_ + d]);
    }

    const float* W1h = W1 + (size_t)h*DH_*DHID_;
    const float* W2h = W2 + (size_t)h*DHID_*DKER_;

    float acc2[8][4];
    #pragma unroll
    for (int j=0;j<8;j++) for (int c=0;c<4;c++) acc2[j][c]=0.f;

    for (int c0 = 0; c0 < 4; c0++) {
        int n0 = c0*64;
        for (int idx = tid; idx < 64*64; idx += 256) {
            int k = idx >> 6, n = idx & 63;
            W1s[n*68 + k] = to_tf32(W1h[(size_t)k*DHID_ + n0 + n]);
        }
        __syncthreads();

        float acc1[2][4][4];
        #pragma unroll
        for (int i=0;i<2;i++) for (int j=0;j<4;j++) for (int c=0;c<4;c++) acc1[i][j][c]=0.f;
        #pragma unroll
        for (int k0=0;k0<64;k0+=8) {
            float a[2][4], bf[4][2];
            #pragma unroll
            for (int i=0;i<2;i++) {
                int rb = wm*32 + i*16;
                a[i][0] = Xs[(rb+g  )*68 + k0+tg  ];
                a[i][1] = Xs[(rb+g+8)*68 + k0+tg  ];
                a[i][2] = Xs[(rb+g  )*68 + k0+tg+4];
                a[i][3] = Xs[(rb+g+8)*68 + k0+tg+4];
            }
            #pragma unroll
            for (int j=0;j<4;j++) {
                int nb = wn*32 + j*8 + g;
                bf[j][0] = W1s[nb*68 + k0+tg  ];
                bf[j][1] = W1s[nb*68 + k0+tg+4];
            }
            #pragma unroll
            for (int i=0;i<2;i++)
                #pragma unroll
                for (int j=0;j<4;j++)
                    mma_tf32(acc1[i][j], a[i], bf[j]);
        }
        #pragma unroll
        for (int i=0;i<2;i++) {
            #pragma unroll
            for (int j=0;j<4;j++) {
                int rr = wm*32 + i*16 + g;
                int cc = wn*32 + j*8 + 2*tg;
                *(float2*)&T1s[rr*68 + cc] =
                    make_float2(to_tf32(gelu_t(acc1[i][j][0])), to_tf32(gelu_t(acc1[i][j][1])));
                *(float2*)&T1s[(rr+8)*68 + cc] =
                    make_float2(to_tf32(gelu_t(acc1[i][j][2])), to_tf32(gelu_t(acc1[i][j][3])));
            }
        }
        for (int idx = tid; idx < 64*64; idx += 256) {
            int k = idx >> 6, n = idx & 63;
            W2s[n*68 + k] = to_tf32(W2h[(size_t)(n0 + k)*DKER_ + n]);
        }
        __syncthreads();

        #pragma unroll
        for (int k0=0;k0<64;k0+=8) {
            float a[4], bf[8][2];
            int rb = warp*16;
            a[0] = T1s[(rb+g  )*68 + k0+tg  ];
            a[1] = T1s[(rb+g+8)*68 + k0+tg  ];
            a[2] = T1s[(rb+g  )*68 + k0+tg+4];
            a[3] = T1s[(rb+g+8)*68 + k0+tg+4];
            #pragma unroll
            for (int j=0;j<8;j++) {
                int nb = j*8+g;
                bf[j][0] = W2s[nb*68 + k0+tg  ];
                bf[j][1] = W2s[nb*68 + k0+tg+4];
            }
            #pragma unroll
            for (int j=0;j<8;j++) mma_tf32(acc2[j], a, bf[j]);
        }
    }

    uint32_t* outw = outg + ((size_t)bh*S_ + m0)*32;

    if (!kpath) {
        #pragma unroll
        for (int j=0;j<8;j++) {
            int rr = warp*16 + g, wi = j*4 + tg;
            outw[(size_t)rr*32 + wi] =
                packbf(fabsf(gelu_t(acc2[j][0])), fabsf(gelu_t(acc2[j][1])));
            outw[(size_t)(rr+8)*32 + wi] =
                packbf(fabsf(gelu_t(acc2[j][2])), fabsf(gelu_t(acc2[j][3])));
        }
        return;
    }

    const float* sDh  = sD  + h*DKER_;
    const float* sD2h = sD2 + h*DKER_;
    __syncthreads();
    #pragma unroll
    for (int j=0;j<8;j++) {
        int rr = warp*16 + g, cc = j*8 + 2*tg;
        T1s[rr*68 + cc  ]     = fabsf(sDh[cc  ]) * gelu_t(acc2[j][0]);
        T1s[rr*68 + cc+1]     = fabsf(sDh[cc+1]) * gelu_t(acc2[j][1]);
        T1s[(rr+8)*68 + cc  ] = fabsf(sDh[cc  ]) * gelu_t(acc2[j][2]);
        T1s[(rr+8)*68 + cc+1] = fabsf(sDh[cc+1]) * gelu_t(acc2[j][3]);
    }
    const float* Wih = Wint + (size_t)h*DKER_*DKER_;
    for (int idx = tid; idx < 64*64; idx += 256) {
        int k = idx >> 6, n = idx & 63;
        W1s[n*68 + k] = to_tf32(Wih[(size_t)k*DKER_ + n]);
    }
    __syncthreads();

    float ac2[8][4];
    #pragma unroll
    for (int j=0;j<8;j++) for (int c=0;c<4;c++) ac2[j][c]=0.f;
    #pragma unroll
    for (int k0=0;k0<64;k0+=8) {
        float a[4], bf[8][2];
        int rb = warp*16;
        a[0] = to_tf32(T1s[(rb+g  )*68 + k0+tg  ]);
        a[1] = to_tf32(T1s[(rb+g+8)*68 + k0+tg  ]);
        a[2] = to_tf32(T1s[(rb+g  )*68 + k0+tg+4]);
        a[3] = to_tf32(T1s[(rb+g+8)*68 + k0+tg+4]);
        #pragma unroll
        for (int j=0;j<8;j++) {
            int nb = j*8+g;
            bf[j][0] = W1s[nb*68 + k0+tg  ];
            bf[j][1] = W1s[nb*68 + k0+tg+4];
        }
        #pragma unroll
        for (int j=0;j<8;j++) mma_tf32(ac2[j], a, bf[j]);
    }

    #pragma unroll
    for (int j=0;j<8;j++) {
        int rr = warp*16 + g, cc = j*8 + 2*tg;
        int wi = j*4 + tg;
        float t00 = T1s[rr*68 + cc  ],     t01 = T1s[rr*68 + cc+1];
        float t10 = T1s[(rr+8)*68 + cc],   t11 = T1s[(rr+8)*68 + cc+1];
        outw[(size_t)rr*32 + wi] =
            packbf(fabsf(t00 + ac2[j][0]*sD2h[cc  ]),
                   fabsf(t01 + ac2[j][1]*sD2h[cc+1]));
        outw[(size_t)(rr+8)*32 + wi] =
            packbf(fabsf(t10 + ac2[j][2]*sD2h[cc  ]),
                   fabsf(t11 + ac2[j][3]*sD2h[cc+1]));
    }
}

// ---------------------------------------------------------------------------
// Attention: bf16 scores (warp = 16 rows x ALL 64 cols), P in registers,
// tf32 PV from score C-fragments. saw staged per-warp via cp.async into smem.
// ONE __syncthreads per tile.
// Per tile t (KV(t)+saw(t) groups pending at loop top):
//   WAIT(0) -> sync -> mask LDG (early) -> issue KV(t+1)
//   -> score MMA(t) -> epilogue (LDS saw from Ss, transform sacc)
//   -> issue saw(t+1) (own rows) -> PV(t)
// smem: Qs[128*36]w Ks[2*64*36]w Vts[2*64*68]f Ss[128*72]f = 108544 B -> 2 CTAs/SM
// ---------------------------------------------------------------------------
__global__ __launch_bounds__(256, 2)
void attn_kernel(const float* __restrict__ sp_lse, const float* __restrict__ saw,
                 float* __restrict__ outp) {
    extern __shared__ uint32_t smw[];
    uint32_t* Qs  = smw;                     // 128*36 (bf16x2)
    uint32_t* Ks  = Qs + 128*36;             // 2*64*36 (bf16x2)
    float*    Vts = (float*)(Ks + 2*64*36);  // 2*64*68 f32 (V^T tiles [e][t])
    float*    Ss  = Vts + 2*64*68;           // 128*72 f32 (saw staging, per-warp rows)

    int bh = blockIdx.y, b = bh >> 4, h = bh & 15;
    int m0 = blockIdx.x * 128;
    int tid = threadIdx.x, warp = tid>>5, lane = tid&31, g = lane>>2, tg = lane&3;

    // Q tile (bf16 words)
    const uint32_t* qsrc = g_qf_w + ((size_t)bh*S_ + m0)*32;
    for (int idx = tid; idx < 4096; idx += 256) {
        int r = idx >> 5, c = idx & 31;
        Qs[r*36 + c] = qsrc[idx];
    }

    const char* kbase  = (const char*)(g_kf_w + (size_t)bh*S_*32);
    const char* vtbase = (const char*)(g_vt + (size_t)bh*64*S_);
    const float* sawb  = saw + (size_t)bh*S_*S_;

    // ldmatrix lane addressing
    int mrow = lane & 15;
    int mwo  = (lane >> 4) << 2;

    // saw staging addressing: lane pair (row r = lane>>1, half = lane&1)
    int srow_l = lane >> 1, shalf = lane & 1;
    uint32_t sdst = smaddr(Ss + ((warp*16 + srow_l)*72 + shalf*32));
    const char* ssrc_row = (const char*)(sawb + (size_t)(m0 + warp*16 + srow_l)*S_) + shalf*128;

    // prologue: KV(0) [group], saw(0) [group]
    {
        #pragma unroll
        for (int c2 = 0; c2 < 2; c2++) {
            int qi = tid + c2*256, r = qi >> 3, cc = qi & 7;
            CPA16(smaddr(Ks + r*36) + cc*16, kbase + (size_t)r*128 + cc*16);
        }
        #pragma unroll
        for (int c2 = 0; c2 < 4; c2++) {
            int qi = tid + c2*256, r = qi >> 4, cc = qi & 15;
            CPA16(smaddr(Vts + r*68) + cc*16, vtbase + (size_t)r*(S_*4) + cc*16);
        }
        CPA_COMMIT();
        #pragma unroll
        for (int c = 0; c < 8; c++)
            CPA16(sdst + c*16, ssrc_row + c*16);
        CPA_COMMIT();
    }

    float oacc[8][4];
    #pragma unroll
    for (int j=0;j<8;j++) for (int c=0;c<4;c++) oacc[j][c]=0.f;
    float rsl[2] = {0.f, 0.f};

    int rg0 = m0 + warp*16 + g;   // this thread's first row

    for (int t = 0; t < 32; t++) {
        int pt = t & 1;

        // (1) KV(t) + saw(t) ready, then barrier
        CPA_WAIT(0);
        __syncthreads();

        // (2) mask words early (L2-resident; covered by score MMA)
        uint32_t mwd[2][2];
        #pragma unroll
        for (int p=0;p<2;p++) {
            mwd[p][0] = g_maskbits[((size_t)(b*S_ + rg0 + 8*p))*64 + t*2    ];
            mwd[p][1] = g_maskbits[((size_t)(b*S_ + rg0 + 8*p))*64 + t*2 + 1];
        }

        // (3) KV(t+1) cp.async into parity pt^1
        if (t < 31) {
            size_t t0n = (size_t)(t+1)*64;
            uint32_t* Kd = Ks  + (pt^1)*64*36;
            float*    Vd = Vts + (pt^1)*64*68;
            #pragma unroll
            for (int c2 = 0; c2 < 2; c2++) {
                int qi = tid + c2*256, r = qi >> 3, cc = qi & 7;
                CPA16(smaddr(Kd + r*36) + cc*16, kbase + (t0n + r)*128 + cc*16);
            }
            #pragma unroll
            for (int c2 = 0; c2 < 4; c2++) {
                int qi = tid + c2*256, r = qi >> 4, cc = qi & 15;
                CPA16(smaddr(Vd + r*68) + cc*16,
                      vtbase + (size_t)r*(S_*4) + t0n*4 + cc*16);
            }
        }
        CPA_COMMIT();

        // (4) score MMA(t): warp computes rows 16w..16w+15 x all 64 cols
        float sacc[8][4];
        #pragma unroll
        for (int j=0;j<8;j++) for (int c=0;c<4;c++) sacc[j][c]=0.f;
        {
            const uint32_t* Kb = Ks + pt*64*36;
            uint32_t qa = smaddr(Qs + (warp*16 + mrow)*36 + mwo);
            uint32_t ka = smaddr(Kb + mrow*36 + mwo);
            #pragma unroll
            for (int kw = 0; kw < 32; kw += 8) {
                uint32_t av[4], bv[4][4];
                ldsm_x4(av, qa + kw*4);
                #pragma unroll
                for (int c = 0; c < 4; c++)
                    ldsm_x4(bv[c], ka + c*(16*36*4) + kw*4);
                #pragma unroll
                for (int j = 0; j < 8; j++)
                    mma_bf16(sacc[j], av, bv[j>>1][j&1], bv[j>>1][(j&1)+2]);
            }
        }

        // (5) epilogue: saw from smem staging (LDS), transform sacc in place
        {
            const float* Sw = Ss + warp*16*72;
            #pragma unroll
            for (int jh = 0; jh < 2; jh++) {
                float2 sv[4][2];
                #pragma unroll
                for (int p=0;p<2;p++) {
                    const float* srow = Sw + (g + 8*p)*72 + jh*32;
                    #pragma unroll
                    for (int jj=0;jj<4;jj++)
                        sv[jj][p] = *(const float2*)(srow + jj*8 + 2*tg);
                }
                #pragma unroll
                for (int jj=0;jj<4;jj++) {
                    int j = jh*4 + jj;
                    int bit = jj*8 + 2*tg;
                    #pragma unroll
                    for (int p=0;p<2;p++) {
                        uint32_t word = mwd[p][jh];
                        bool b0m = (word >> bit) & 1u;
                        bool b1m = (word >> (bit+1)) & 1u;
                        float s0 = sacc[j][2*p], s1 = sacc[j][2*p+1];
                        float n0 = b0m ? s0 + 1e-6f : __expf(sv[jj][p].x);
                        float n1 = b1m ? s1 + 1e-6f : __expf(sv[jj][p].y);
                        rsl[p] += (b0m ? s0 : 0.f) + (b1m ? s1 : 0.f);
                        sacc[j][2*p]   = to_tf32(n0);
                        sacc[j][2*p+1] = to_tf32(n1);
                    }
                }
            }
        }

        // pin the Ss reads above before overwriting via cp.async
        asm volatile("" ::: "memory");

        // (6) saw(t+1) cp.async into this warp's own Ss rows
        if (t < 31) {
            const char* ssrc = ssrc_row + (size_t)(t+1)*256;
            #pragma unroll
            for (int c = 0; c < 8; c++)
                CPA16(sdst + c*16, ssrc + c*16);
        }
        CPA_COMMIT();

        // (7) PV(t): P from registers (C-frag -> A-frag reorder), V^T from smem
        {
            const float* Vb = Vts + pt*64*68;
            #pragma unroll
            for (int j = 0; j < 8; j++) {
                float a[4] = {sacc[j][0], sacc[j][2], sacc[j][1], sacc[j][3]};
                #pragma unroll
                for (int ng = 0; ng < 8; ng++) {
                    float2 b2 = *(const float2*)&Vb[(ng*8+g)*68 + j*8 + 2*tg];
                    float bf[2] = {b2.x, b2.y};
                    mma_tf32(oacc[ng], a, bf);
                }
            }
        }
    }

    // row sums: quad butterfly over tg -> every lane has its rows' sums
    #pragma unroll
    for (int p=0;p<2;p++) {
        rsl[p] += __shfl_xor_sync(0xffffffffu, rsl[p], 1);
        rsl[p] += __shfl_xor_sync(0xffffffffu, rsl[p], 2);
    }

    const float* spb = sp_lse + (size_t)bh*S_ + m0;
    float* ob = outp + ((size_t)(b*S_ + m0))*D_ + h*DH_;
    int r0 = warp*16 + g;
    float den0 = 1.0f / (rsl[0] + 1e-6f + __expf(spb[r0  ]));
    float den1 = 1.0f / (rsl[1] + 1e-6f + __expf(spb[r0+8]));
    #pragma unroll
    for (int j=0;j<8;j++) {
        int cc = j*8 + 2*tg;
        *(float2*)&ob[(size_t)r0*D_ + cc] =
            make_float2(oacc[j][0]*den0, oacc[j][1]*den0);
        *(float2*)&ob[(size_t)(r0+8)*D_ + cc] =
            make_float2(oacc[j][2]*den1, oacc[j][3]*den1);
    }
}

// ---------------------------------------------------------------------------
extern "C" void kernel_launch(void* const* d_in, const int* in_sizes, int n_in,
                              void* d_out, int out_size) {
    (void)in_sizes; (void)n_in; (void)out_size;
    const float*   q    = (const float*)d_in[1];
    const float*   k    = (const float*)d_in[2];
    const float*   v    = (const float*)d_in[3];
    const void*    mask = d_in[4];
    const float*   sp   = (const float*)d_in[5];
    const float*   saw  = (const float*)d_in[6];
    const float*   Wq1  = (const float*)d_in[8];
    const float*   Wk1  = (const float*)d_in[9];
    const float*   Wq2  = (const float*)d_in[10];
    const float*   Wk2  = (const float*)d_in[11];
    const float*   Wint = (const float*)d_in[12];
    const float*   sD   = (const float*)d_in[13];
    const float*   sD2  = (const float*)d_in[14];
    float* outp = (float*)d_out;

    const int SMEMF = (128*68 + 64*68 + 64*68 + 128*68) * 4;         // 104448
    const int SMEMA = (128*36 + 2*64*36 + 2*64*68 + 128*72) * 4;     // 108544

    cudaFuncSetAttribute(fused_kernel, cudaFuncAttributeMaxDynamicSharedMemorySize, SMEMF);
    cudaFuncSetAttribute(attn_kernel,  cudaFuncAttributeMaxDynamicSharedMemorySize, SMEMA);

    maskbits_kernel<<<1024, 256>>>(mask);
    vt_kernel<<<dim3(32, BH_), 256>>>(v);
    fused_kernel<<<dim3(16, BH_, 2), 256, SMEMF>>>(q, k, Wq1, Wk1, Wq2, Wk2, Wint, sD, sD2);
    attn_kernel<<<dim3(16, BH_), 256, SMEMA>>>(sp, saw, outp);
}